// round 12
// baseline (speedup 1.0000x reference)
#include <cuda_runtime.h>
#include <cuda_fp16.h>
#include <math.h>
#include <stdint.h>

// ---------------------------------------------------------------------------
// Problem constants (Mamba2 block, B=2, L=4096)
// ---------------------------------------------------------------------------
namespace cfg {
constexpr int D_MODEL   = 2048;
constexpr int D_INNER   = 4096;
constexpr int D_STATE   = 64;
constexpr int D_CONV    = 4;
constexpr int NHEADS    = 64;
constexpr int HEADDIM   = 64;
constexpr int D_XBC     = D_INNER + 2 * D_STATE;              // 4224
constexpr int D_IN_PROJ = 2 * D_INNER + 2 * D_STATE + NHEADS; // 8384
constexpr int LSEQ      = 4096;
constexpr int BATCH     = 2;
constexpr int BL        = BATCH * LSEQ;                       // 8192
constexpr int CHUNK     = 64;
constexpr int NCHUNK    = LSEQ / CHUNK;                       // 64
constexpr int NBH       = BATCH * NHEADS;                     // 128
constexpr int N1_PAD    = 8448;                               // 33 * 256
}

// ---------------------------------------------------------------------------
// Scratch (allocation-free: __device__ globals; zero-init at load)
// ---------------------------------------------------------------------------
__device__ float g_zx [(size_t)cfg::BL * cfg::D_IN_PROJ];
__device__ float g_xbc[(size_t)cfg::BL * cfg::D_XBC];
__device__ float g_dt [(size_t)cfg::BL * cfg::NHEADS];
__device__ float g_y  [(size_t)cfg::BL * cfg::D_INNER];

// SSD intermediates
__device__ float g_G    [(size_t)cfg::NBH * cfg::NCHUNK * 64 * 64];
__device__ float g_sprev[(size_t)cfg::NBH * cfg::NCHUNK * 64 * 64];
__device__ float g_acum [(size_t)cfg::NBH * cfg::NCHUNK * 64];

// fp16 operands, PRE-SWIZZLED 16KB tiles (128 rows x 64 cols)
__device__ __half g_uh [(size_t)cfg::BL * cfg::D_MODEL];
__device__ __half g_wih[(size_t)cfg::N1_PAD * cfg::D_MODEL];
__device__ __half g_nmh[(size_t)cfg::BL * cfg::D_INNER];
__device__ __half g_woh[(size_t)cfg::D_MODEL * cfg::D_INNER];

// ---------------------------------------------------------------------------
// PTX helpers
// ---------------------------------------------------------------------------
__device__ __forceinline__ uint32_t smem_u32(const void* p) {
    uint32_t a;
    asm("{ .reg .u64 t; cvta.to.shared.u64 t, %1; cvt.u32.u64 %0, t; }"
        : "=r"(a) : "l"(p));
    return a;
}
__device__ __forceinline__ void ldsm4(uint32_t r[4], uint32_t addr) {
    asm volatile("ldmatrix.sync.aligned.m8n8.x4.shared.b16 {%0,%1,%2,%3}, [%4];"
                 : "=r"(r[0]), "=r"(r[1]), "=r"(r[2]), "=r"(r[3]) : "r"(addr));
}
__device__ __forceinline__ void ldsm2(uint32_t r[2], uint32_t addr) {
    asm volatile("ldmatrix.sync.aligned.m8n8.x2.shared.b16 {%0,%1}, [%2];"
                 : "=r"(r[0]), "=r"(r[1]) : "r"(addr));
}
__device__ __forceinline__ void mma16816h(float c[4], const uint32_t a[4],
                                          uint32_t b0, uint32_t b1) {
    asm volatile(
        "mma.sync.aligned.m16n8k16.row.col.f32.f16.f16.f32 "
        "{%0,%1,%2,%3}, {%4,%5,%6,%7}, {%8,%9}, {%0,%1,%2,%3};"
        : "+f"(c[0]), "+f"(c[1]), "+f"(c[2]), "+f"(c[3])
        : "r"(a[0]), "r"(a[1]), "r"(a[2]), "r"(a[3]), "r"(b0), "r"(b1));
}
__device__ __forceinline__ void bulk_cp(uint32_t dst, const void* src,
                                        uint32_t bytes, uint32_t mbar) {
    asm volatile(
        "cp.async.bulk.shared::cta.global.mbarrier::complete_tx::bytes "
        "[%0], [%1], %2, [%3];"
        :: "r"(dst), "l"(src), "r"(bytes), "r"(mbar) : "memory");
}
#define MBARRIER_INIT(addr, cnt) \
    asm volatile("mbarrier.init.shared.b64 [%0], %1;" :: "r"(addr), "r"(cnt) : "memory")
#define MBARRIER_EXPECT_TX(addr, bytes) \
    asm volatile("mbarrier.arrive.expect_tx.shared.b64 _, [%0], %1;" \
                 :: "r"(addr), "r"(bytes) : "memory")
#define MBARRIER_WAIT_PARITY(addr, par) do {                                      \
    uint32_t _m = (addr); uint32_t _p = (par); uint32_t _done;                    \
    asm volatile("{\n\t.reg .pred p;\n\t"                                         \
        "mbarrier.try_wait.parity.acquire.cta.shared::cta.b64 p, [%1], %2;\n\t"   \
        "selp.b32 %0, 1, 0, p;\n\t}" : "=r"(_done) : "r"(_m), "r"(_p) : "memory");\
    if (!_done) {                                                                 \
        asm volatile("{\n\t.reg .pred P1;\n\t"                                    \
        "WL_%=:\n\t"                                                              \
        "mbarrier.try_wait.parity.acquire.cta.shared::cta.b64 P1, [%0], %1, 0x989680;\n\t" \
        "@P1 bra.uni WD_%=;\n\tbra.uni WL_%=;\n\tWD_%=:\n\t}"                     \
        :: "r"(_m), "r"(_p) : "memory");                                          \
    } } while (0)

__device__ __forceinline__ int swz_idx(int row, int col) {
    return row * 64 + (((col >> 3) ^ (row & 7)) << 3) + (col & 7);
}

// ---------------------------------------------------------------------------
// HMMA fp16 GEMM on pre-swizzled tiles. Block 128x256x64, 8 warps (2x4),
// warp tile 64x64 (halved smem bytes/MAC vs 64x32). 1 CTA/SM, 3-slot
// bulk-copy pipeline (A tile + 2 B tiles per stage).
// ---------------------------------------------------------------------------
namespace mg {
constexpr int KT    = 64;
constexpr int TILEB = 128 * KT * 2;          // 16384 B (one 128x64 tile)
constexpr int STAGE = 3 * TILEB;             // 49152 B (A, B0, B1)
constexpr int STAGES = 3;
constexpr int MBAR_OFF = STAGES * STAGE;     // 147456
constexpr int SMEM_BYTES = MBAR_OFF + 64;
}

__global__ __launch_bounds__(256, 1) void gemm_mma_kernel(
    const __half* __restrict__ At, const __half* __restrict__ Bt,
    float* __restrict__ C, int M, int N, int K)
{
    extern __shared__ char smraw[];
    const uint32_t sb = smem_u32(smraw);
    const int tid  = threadIdx.x;
    const int bm   = blockIdx.y * 128;
    const int bn   = blockIdx.x * 256;
    const int wid  = tid >> 5, lane = tid & 31;
    const int wm   = wid & 1;         // 0..1 : 64-row half
    const int wn   = wid >> 1;        // 0..3 : 64-col quarter
    const int NK   = K >> 6;

    const __half* Abase  = At + (size_t)blockIdx.y * NK * 8192;
    const __half* B0base = Bt + (size_t)(blockIdx.x * 2)     * NK * 8192;
    const __half* B1base = Bt + (size_t)(blockIdx.x * 2 + 1) * NK * 8192;
    const uint32_t mb = sb + mg::MBAR_OFF;

    if (tid == 0) {
        MBARRIER_INIT(mb,      1u);
        MBARRIER_INIT(mb + 8,  1u);
        MBARRIER_INIT(mb + 16, 1u);
    }
    __syncthreads();

    auto issue = [&](int stage, int kblk) {
        const uint32_t m = mb + stage * 8;
        MBARRIER_EXPECT_TX(m, (uint32_t)mg::STAGE);
        const uint32_t d = sb + stage * mg::STAGE;
        bulk_cp(d,                 Abase  + (size_t)kblk * 8192, mg::TILEB, m);
        bulk_cp(d + mg::TILEB,     B0base + (size_t)kblk * 8192, mg::TILEB, m);
        bulk_cp(d + 2 * mg::TILEB, B1base + (size_t)kblk * 8192, mg::TILEB, m);
    };

    float acc[4][8][4];
#pragma unroll
    for (int i = 0; i < 4; i++)
#pragma unroll
        for (int j = 0; j < 8; j++)
#pragma unroll
            for (int q = 0; q < 4; q++) acc[i][j][q] = 0.f;

    if (tid == 0) { issue(0, 0); issue(1, 1); }

    // per-warp B smem base: wn 0,1 -> B0 tile, wn 2,3 -> B1 tile
    const uint32_t bTileOff = mg::TILEB + (uint32_t)(wn >> 1) * mg::TILEB;
    const int nbase = (wn & 1) * 64;   // row base inside the 128-row B tile

    for (int kb = 0; kb < NK; kb++) {
        const int st = kb % mg::STAGES;
        MBARRIER_WAIT_PARITY(mb + st * 8, (uint32_t)((kb / 3) & 1));
        __syncthreads();

        if (kb + 2 < NK && tid == 0)
            issue((kb + 2) % mg::STAGES, kb + 2);

        const uint32_t sA = sb + st * mg::STAGE;
        const uint32_t sB = sA + bTileOff;

#pragma unroll
        for (int ks = 0; ks < 4; ks++) {
            // B: 4 ldsm4, each covering 2 n-tiles (both k16 halves)
            uint32_t bfr[4][4];
#pragma unroll
            for (int pp = 0; pp < 4; pp++) {
                int nr = nbase + pp * 16 + ((lane >> 4) & 1) * 8 + (lane & 7);
                int g  = 2 * ks + ((lane >> 3) & 1);
                ldsm4(bfr[pp], sB + nr * 128 + ((g ^ (nr & 7)) << 4));
            }
            uint32_t a[4][4];
#pragma unroll
            for (int mt = 0; mt < 4; mt++) {
                int ar = wm * 64 + mt * 16 + (lane & 15);
                int g  = 2 * ks + (lane >> 4);
                ldsm4(a[mt], sA + ar * 128 + ((g ^ (ar & 7)) << 4));
            }
#pragma unroll
            for (int mt = 0; mt < 4; mt++)
#pragma unroll
                for (int pp = 0; pp < 4; pp++) {
                    mma16816h(acc[mt][2 * pp],     a[mt], bfr[pp][0], bfr[pp][1]);
                    mma16816h(acc[mt][2 * pp + 1], a[mt], bfr[pp][2], bfr[pp][3]);
                }
        }
    }

#pragma unroll
    for (int mt = 0; mt < 4; mt++) {
#pragma unroll
        for (int nt = 0; nt < 8; nt++) {
            int row = bm + wm * 64 + mt * 16 + (lane >> 2);
            int col = bn + wn * 64 + nt * 8 + (lane & 3) * 2;
            if (col < N) {
                *(float2*)(C + (size_t)row * N + col) =
                    make_float2(acc[mt][nt][0], acc[mt][nt][1]);
                *(float2*)(C + (size_t)(row + 8) * N + col) =
                    make_float2(acc[mt][nt][2], acc[mt][nt][3]);
            }
        }
    }
}

// ---------------------------------------------------------------------------
// fp32 row-major -> fp16 pre-swizzled 16KB tiles (unchanged)
// ---------------------------------------------------------------------------
__global__ __launch_bounds__(256) void cvt_swz_kernel(
    const float* __restrict__ src, __half* __restrict__ dst, int Mreal, int K)
{
    const int NKt = K >> 6;
    const int tile = blockIdx.x;
    const int tm = tile / NKt, tk = tile % NKt;
    __half* d = dst + (size_t)tile * 8192;
#pragma unroll
    for (int it = 0; it < 4; it++) {
        int id = it * 256 + threadIdx.x;
        int r  = id >> 3, g = id & 7;
        int grow = tm * 128 + r;
        uint32_t off = (uint32_t)(r * 64 + ((g ^ (r & 7)) << 3));
        uint4 pk;
        if (grow < Mreal) {
            const float* s = src + (size_t)grow * K + tk * 64 + g * 8;
            float4 v0 = *(const float4*)s;
            float4 v1 = *(const float4*)(s + 4);
            __half2 h0 = __floats2half2_rn(v0.x, v0.y);
            __half2 h1 = __floats2half2_rn(v0.z, v0.w);
            __half2 h2 = __floats2half2_rn(v1.x, v1.y);
            __half2 h3 = __floats2half2_rn(v1.z, v1.w);
            pk.x = *(uint32_t*)&h0; pk.y = *(uint32_t*)&h1;
            pk.z = *(uint32_t*)&h2; pk.w = *(uint32_t*)&h3;
        } else {
            pk = make_uint4(0, 0, 0, 0);
        }
        *(uint4*)(d + off) = pk;
    }
}

// ---------------------------------------------------------------------------
// Fused conv+silu and dt softplus (unchanged)
// ---------------------------------------------------------------------------
namespace fc {
constexpr int NCONV = (cfg::BL * cfg::D_XBC + 255) / 256;
constexpr int NDT   = (cfg::BL * cfg::NHEADS + 255) / 256;
}

__global__ void conv_dt_kernel(const float* __restrict__ zx,
                               const float* __restrict__ cw,
                               const float* __restrict__ cb,
                               const float* __restrict__ dt_bias,
                               float* __restrict__ xbc_out,
                               float* __restrict__ dt_out)
{
    int blk = blockIdx.x;
    if (blk < fc::NCONV) {
        int idx = blk * 256 + threadIdx.x;
        if (idx >= cfg::BL * cfg::D_XBC) return;
        int j = idx % cfg::D_XBC;
        int t = idx / cfg::D_XBC;
        int l = t & (cfg::LSEQ - 1);
        int b = t >> 12;
        float v = cb[j];
#pragma unroll
        for (int k = 0; k < cfg::D_CONV; k++) {
            int ls = l + k - (cfg::D_CONV - 1);
            if (ls >= 0)
                v = fmaf(cw[j * cfg::D_CONV + k],
                         zx[(size_t)(b * cfg::LSEQ + ls) * cfg::D_IN_PROJ + cfg::D_INNER + j], v);
        }
        xbc_out[(size_t)t * cfg::D_XBC + j] = v / (1.f + expf(-v));
    } else {
        int idx = (blk - fc::NCONV) * 256 + threadIdx.x;
        if (idx >= cfg::BL * cfg::NHEADS) return;
        int h = idx & 63;
        int t = idx >> 6;
        float x = zx[(size_t)t * cfg::D_IN_PROJ + cfg::D_INNER + cfg::D_XBC + h] + dt_bias[h];
        dt_out[idx] = (x > 20.f) ? x : log1pf(expf(x));
    }
}

// ---------------------------------------------------------------------------
// SSD pass 1 (HMMA, unchanged from R11 WIN)
// ---------------------------------------------------------------------------
__global__ __launch_bounds__(256) void ssd_pass1(
    const float* __restrict__ xbc, const float* __restrict__ dtg,
    const float* __restrict__ A_log,
    float* __restrict__ G, float* __restrict__ acum)
{
    __shared__ __half Bw[4096];
    __shared__ __half Xt[4096];
    __shared__ float Acum[64], ws[64], dts[64];
    const int blk = blockIdx.x;
    const int c = blk & 63, bh = blk >> 6;
    const int h = bh & 63, b = bh >> 6;
    const int tid = threadIdx.x;
    const float Aneg = -expf(A_log[h]);
    const int l0g = c * cfg::CHUNK;

    if (tid < 64) {
        const int lane = tid & 31;
        size_t row = (size_t)(b * cfg::LSEQ + l0g + tid);
        float dtv = dtg[row * cfg::NHEADS + h];
        dts[tid] = dtv;
        float v = Aneg * dtv;
#pragma unroll
        for (int o = 1; o < 32; o <<= 1) {
            float n = __shfl_up_sync(0xffffffffu, v, o);
            if (lane >= o) v += n;
        }
        Acum[tid] = v;
    }
    __syncthreads();
    if (tid < 64) {
        float v = Acum[tid] + ((tid >= 32) ? Acum[31] : 0.f);
        Acum[tid] = v;
    }
    __syncthreads();
    if (tid < 64) {
        ws[tid] = expf(Acum[63] - Acum[tid]);
        acum[(size_t)blk * 64 + tid] = Acum[tid];
    }
    __syncthreads();

    for (int idx = tid; idx < 1024; idx += 256) {
        int l = idx >> 4, q4 = (idx & 15) * 4;
        size_t row = (size_t)(b * cfg::LSEQ + l0g + l);
        const float* xr = xbc + row * cfg::D_XBC;
        float dtv = dts[l], wv = ws[l];
        float4 xv = *(const float4*)(xr + h * cfg::HEADDIM + q4);
        float4 bv = *(const float4*)(xr + cfg::D_INNER + q4);
        float xa[4] = {xv.x, xv.y, xv.z, xv.w};
        float ba[4] = {bv.x, bv.y, bv.z, bv.w};
#pragma unroll
        for (int e = 0; e < 4; e++) {
            int p = q4 + e;
            Xt[swz_idx(p, l)] = __float2half_rn(xa[e] * dtv);
            Bw[swz_idx(p, l)] = __float2half_rn(ba[e] * wv);
        }
    }
    __syncthreads();

    const int wid = tid >> 5, lane = tid & 31;
    const int wr = wid & 3, wc = wid >> 2;
    const uint32_t sBw = smem_u32(Bw), sXt = smem_u32(Xt);
    float acc[4][4];
#pragma unroll
    for (int i = 0; i < 4; i++)
#pragma unroll
        for (int j = 0; j < 4; j++) acc[i][j] = 0.f;

#pragma unroll
    for (int ks = 0; ks < 4; ks++) {
        uint32_t a[4];
        {
            int ar = wr * 16 + (lane & 15);
            int g  = 2 * ks + (lane >> 4);
            ldsm4(a, sBw + ar * 128 + ((g ^ (ar & 7)) << 4));
        }
#pragma unroll
        for (int nt = 0; nt < 4; nt++) {
            uint32_t bb[2];
            int nr = wc * 32 + nt * 8 + (lane & 7);
            int g  = 2 * ks + ((lane >> 3) & 1);
            ldsm2(bb, sXt + nr * 128 + ((g ^ (nr & 7)) << 4));
            mma16816h(acc[nt], a, bb[0], bb[1]);
        }
    }

    float* gout = G + (size_t)blk * 4096;
    const int n0 = wr * 16 + (lane >> 2);
#pragma unroll
    for (int nt = 0; nt < 4; nt++) {
        int p = wc * 32 + nt * 8 + (lane & 3) * 2;
        *(float2*)(gout + n0 * 64 + p)       = make_float2(acc[nt][0], acc[nt][1]);
        *(float2*)(gout + (n0 + 8) * 64 + p) = make_float2(acc[nt][2], acc[nt][3]);
    }
}

// ---------------------------------------------------------------------------
// SSD pass 2 (unchanged)
// ---------------------------------------------------------------------------
__global__ __launch_bounds__(256) void ssd_pass2(
    const float* __restrict__ G, const float* __restrict__ acum,
    float* __restrict__ sprev)
{
    __shared__ float eAc[cfg::NCHUNK];
    const int bh    = blockIdx.x >> 2;
    const int slice = blockIdx.x & 3;
    const int tid   = threadIdx.x;
    if (tid < cfg::NCHUNK)
        eAc[tid] = expf(acum[((size_t)bh * cfg::NCHUNK + tid) * 64 + 63]);
    __syncthreads();

    const int f4 = slice * 256 + tid;
    float4 S = make_float4(0.f, 0.f, 0.f, 0.f);
    const size_t bhbase = (size_t)bh * cfg::NCHUNK * 4096;
    for (int c = 0; c < cfg::NCHUNK; c++) {
        const size_t base = bhbase + (size_t)c * 4096 + f4 * 4;
        *(float4*)(sprev + base) = S;
        float4 g = *(const float4*)(G + base);
        float ea = eAc[c];
        S.x = fmaf(ea, S.x, g.x);
        S.y = fmaf(ea, S.y, g.y);
        S.z = fmaf(ea, S.z, g.z);
        S.w = fmaf(ea, S.w, g.w);
    }
}

// ---------------------------------------------------------------------------
// SSD pass 3 (HMMA, unchanged from R11 WIN)
// ---------------------------------------------------------------------------
struct P3S {
    __half Ct [4096];
    __half Bt [4096];
    __half Xt [4096];
    __half Spt[4096];
    __half W2 [4096];
    float  Xraw[4096];
    float  Acum[64], eA[64], dts[64];
};

__global__ __launch_bounds__(256) void ssd_pass3(
    const float* __restrict__ xbc, const float* __restrict__ dtg,
    const float* __restrict__ D_param,
    const float* __restrict__ sprev, const float* __restrict__ acum,
    float* __restrict__ y)
{
    extern __shared__ char smraw[];
    P3S& sm = *reinterpret_cast<P3S*>(smraw);
    const int blk = blockIdx.x;
    const int c = blk & 63, bh = blk >> 6;
    const int h = bh & 63, b = bh >> 6;
    const int tid = threadIdx.x;
    const float Dh = D_param[h];
    const int l0g = c * cfg::CHUNK;

    if (tid < 64) {
        size_t row = (size_t)(b * cfg::LSEQ + l0g + tid);
        sm.dts[tid] = dtg[row * cfg::NHEADS + h];
        float a = acum[(size_t)blk * 64 + tid];
        sm.Acum[tid] = a;
        sm.eA[tid]   = expf(a);
    }
    __syncthreads();

    const float* spin = sprev + (size_t)blk * 4096;
    for (int idx = tid; idx < 1024; idx += 256) {
        int r = idx >> 4, q4 = (idx & 15) * 4;
        size_t grow = (size_t)(b * cfg::LSEQ + l0g + r);
        const float* xr = xbc + grow * cfg::D_XBC;
        float dtv = sm.dts[r];
        float4 xv = *(const float4*)(xr + h * cfg::HEADDIM + q4);
        float4 bv = *(const float4*)(xr + cfg::D_INNER + q4);
        float4 cv = *(const float4*)(xr + cfg::D_INNER + cfg::D_STATE + q4);
        float4 sv = *(const float4*)(spin + r * 64 + q4);

        *(float4*)&sm.Xraw[r * 64 + q4] = xv;
        {
            __half2 c0 = __floats2half2_rn(cv.x, cv.y);
            __half2 c1 = __floats2half2_rn(cv.z, cv.w);
            __half2 b0 = __floats2half2_rn(bv.x, bv.y);
            __half2 b1 = __floats2half2_rn(bv.z, bv.w);
            int ci = swz_idx(r, q4);
            uint2 pc; pc.x = *(uint32_t*)&c0; pc.y = *(uint32_t*)&c1;
            uint2 pb; pb.x = *(uint32_t*)&b0; pb.y = *(uint32_t*)&b1;
            *(uint2*)&sm.Ct[ci] = pc;
            *(uint2*)&sm.Bt[ci] = pb;
        }
        float xa[4] = {xv.x, xv.y, xv.z, xv.w};
        float sa[4] = {sv.x, sv.y, sv.z, sv.w};
#pragma unroll
        for (int e = 0; e < 4; e++) {
            int p = q4 + e;
            sm.Xt [swz_idx(p, r)] = __float2half_rn(xa[e] * dtv);
            sm.Spt[swz_idx(p, r)] = __float2half_rn(sa[e]);
        }
    }
    __syncthreads();

    const int wid = tid >> 5, lane = tid & 31;
    const int wr = wid & 3, wc = wid >> 2;
    const uint32_t sCt = smem_u32(sm.Ct),  sBt = smem_u32(sm.Bt);
    const uint32_t sXt = smem_u32(sm.Xt),  sSp = smem_u32(sm.Spt);
    const uint32_t sW2 = smem_u32(sm.W2);
    const int l0 = wr * 16 + (lane >> 2);

    {
        float accw[4][4];
#pragma unroll
        for (int i = 0; i < 4; i++)
#pragma unroll
            for (int j = 0; j < 4; j++) accw[i][j] = 0.f;
#pragma unroll
        for (int ks = 0; ks < 4; ks++) {
            uint32_t a[4];
            int ar = wr * 16 + (lane & 15);
            int ga = 2 * ks + (lane >> 4);
            ldsm4(a, sCt + ar * 128 + ((ga ^ (ar & 7)) << 4));
#pragma unroll
            for (int nt = 0; nt < 4; nt++) {
                uint32_t bb[2];
                int sr = wc * 32 + nt * 8 + (lane & 7);
                int gb = 2 * ks + ((lane >> 3) & 1);
                ldsm2(bb, sBt + sr * 128 + ((gb ^ (sr & 7)) << 4));
                mma16816h(accw[nt], a, bb[0], bb[1]);
            }
        }
        float A0 = sm.Acum[l0], A1 = sm.Acum[l0 + 8];
#pragma unroll
        for (int nt = 0; nt < 4; nt++) {
            int s0 = wc * 32 + nt * 8 + (lane & 3) * 2;
            float As0 = sm.Acum[s0], As1 = sm.Acum[s0 + 1];
            float w00 = (s0     <= l0) ? expf(A0 - As0) : 0.f;
            float w01 = (s0 + 1 <= l0) ? expf(A0 - As1) : 0.f;
            float w10 = (s0     <= l0 + 8) ? expf(A1 - As0) : 0.f;
            float w11 = (s0 + 1 <= l0 + 8) ? expf(A1 - As1) : 0.f;
            __half2 h0 = __floats2half2_rn(accw[nt][0] * w00, accw[nt][1] * w01);
            __half2 h1 = __floats2half2_rn(accw[nt][2] * w10, accw[nt][3] * w11);
            *(uint32_t*)&sm.W2[swz_idx(l0,     s0)] = *(uint32_t*)&h0;
            *(uint32_t*)&sm.W2[swz_idx(l0 + 8, s0)] = *(uint32_t*)&h1;
        }
    }
    __syncthreads();

    float accd[4][4], acco[4][4];
#pragma unroll
    for (int i = 0; i < 4; i++)
#pragma unroll
        for (int j = 0; j < 4; j++) { accd[i][j] = 0.f; acco[i][j] = 0.f; }

#pragma unroll
    for (int ks = 0; ks < 4; ks++) {
        uint32_t a[4];
        int ar = wr * 16 + (lane & 15);
        int ga = 2 * ks + (lane >> 4);
        ldsm4(a, sW2 + ar * 128 + ((ga ^ (ar & 7)) << 4));
#pragma unroll
        for (int nt = 0; nt < 4; nt++) {
            uint32_t bb[2];
            int nr = wc * 32 + nt * 8 + (lane & 7);
            int gb = 2 * ks + ((lane >> 3) & 1);
            ldsm2(bb, sXt + nr * 128 + ((gb ^ (nr & 7)) << 4));
            mma16816h(accd[nt], a, bb[0], bb[1]);
        }
    }
#pragma unroll
    for (int ks = 0; ks < 4; ks++) {
        uint32_t a[4];
        int ar = wr * 16 + (lane & 15);
        int ga = 2 * ks + (lane >> 4);
        ldsm4(a, sCt + ar * 128 + ((ga ^ (ar & 7)) << 4));
#pragma unroll
        for (int nt = 0; nt < 4; nt++) {
            uint32_t bb[2];
            int nr = wc * 32 + nt * 8 + (lane & 7);
            int gb = 2 * ks + ((lane >> 3) & 1);
            ldsm2(bb, sSp + nr * 128 + ((gb ^ (nr & 7)) << 4));
            mma16816h(acco[nt], a, bb[0], bb[1]);
        }
    }

    const float eA0 = sm.eA[l0], eA1 = sm.eA[l0 + 8];
    const size_t row0 = (size_t)(b * cfg::LSEQ + l0g + l0);
#pragma unroll
    for (int nt = 0; nt < 4; nt++) {
        int p = wc * 32 + nt * 8 + (lane & 3) * 2;
        float x00 = sm.Xraw[l0 * 64 + p],      x01 = sm.Xraw[l0 * 64 + p + 1];
        float x10 = sm.Xraw[(l0 + 8) * 64 + p], x11 = sm.Xraw[(l0 + 8) * 64 + p + 1];
        float2 v0 = make_float2(accd[nt][0] + eA0 * acco[nt][0] + Dh * x00,
                                accd[nt][1] + eA0 * acco[nt][1] + Dh * x01);
        float2 v1 = make_float2(accd[nt][2] + eA1 * acco[nt][2] + Dh * x10,
                                accd[nt][3] + eA1 * acco[nt][3] + Dh * x11);
        *(float2*)(y + row0 * cfg::D_INNER + h * cfg::HEADDIM + p)       = v0;
        *(float2*)(y + (row0 + 8) * cfg::D_INNER + h * cfg::HEADDIM + p) = v1;
    }
}

// ---------------------------------------------------------------------------
// gate + RMSNorm -> fp16 pre-swizzled tiles (unchanged)
// ---------------------------------------------------------------------------
__global__ __launch_bounds__(256) void gate_norm_kernel(
    const float* __restrict__ y, const float* __restrict__ zx,
    const float* __restrict__ nw, __half* __restrict__ nmh)
{
    __shared__ float gbuf[cfg::D_INNER];
    __shared__ float red[8];
    const int t = blockIdx.x;
    const int tid = threadIdx.x;
    const float* yr = y + (size_t)t * cfg::D_INNER;
    const float* zr = zx + (size_t)t * cfg::D_IN_PROJ;

    float ss = 0.f;
    for (int i = tid; i < cfg::D_INNER; i += 256) {
        float zv = zr[i];
        float gv = yr[i] * (zv / (1.f + expf(-zv)));
        gbuf[i] = gv;
        ss = fmaf(gv, gv, ss);
    }
#pragma unroll
    for (int o = 16; o; o >>= 1) ss += __shfl_xor_sync(0xffffffffu, ss, o);
    if ((tid & 31) == 0) red[tid >> 5] = ss;
    __syncthreads();
    if (tid < 32) {
        float v = (tid < 8) ? red[tid] : 0.f;
#pragma unroll
        for (int o = 4; o; o >>= 1) v += __shfl_xor_sync(0xffffffffu, v, o);
        if (tid == 0) red[0] = v;
    }
    __syncthreads();
    const float scale = rsqrtf(red[0] * (1.f / cfg::D_INNER) + 1e-5f);
    const int tm = t >> 7, r = t & 127;
    const size_t tmbase = (size_t)tm * (cfg::D_INNER / 64) * 8192;
    const uint32_t rx = (uint32_t)(r & 7);
    for (int i = tid; i < cfg::D_INNER; i += 256) {
        float val = gbuf[i] * scale * nw[i];
        int tk = i >> 6, g = (i >> 3) & 7, e = i & 7;
        size_t off = tmbase + (size_t)tk * 8192 + r * 64 + ((g ^ rx) << 3) + e;
        nmh[off] = __float2half_rn(val);
    }
}

// ---------------------------------------------------------------------------
// Host launch
// ---------------------------------------------------------------------------
extern "C" void kernel_launch(void* const* d_in, const int* in_sizes, int n_in,
                              void* d_out, int out_size)
{
    (void)in_sizes; (void)n_in; (void)out_size;
    const float* u       = (const float*)d_in[0];
    const float* W_in    = (const float*)d_in[1];
    const float* conv_w  = (const float*)d_in[2];
    const float* conv_b  = (const float*)d_in[3];
    const float* dt_bias = (const float*)d_in[4];
    const float* A_log   = (const float*)d_in[5];
    const float* D_param = (const float*)d_in[6];
    const float* norm_w  = (const float*)d_in[7];
    const float* W_out   = (const float*)d_in[8];
    float* out = (float*)d_out;

    void *pzx, *pxbc, *pdt, *py, *pG, *psp, *pac;
    void *puh, *pwih, *pnmh, *pwoh;
    cudaGetSymbolAddress(&pzx,  g_zx);
    cudaGetSymbolAddress(&pxbc, g_xbc);
    cudaGetSymbolAddress(&pdt,  g_dt);
    cudaGetSymbolAddress(&py,   g_y);
    cudaGetSymbolAddress(&pG,   g_G);
    cudaGetSymbolAddress(&psp,  g_sprev);
    cudaGetSymbolAddress(&pac,  g_acum);
    cudaGetSymbolAddress(&puh,  g_uh);
    cudaGetSymbolAddress(&pwih, g_wih);
    cudaGetSymbolAddress(&pnmh, g_nmh);
    cudaGetSymbolAddress(&pwoh, g_woh);
    float* zx  = (float*)pzx;
    float* xbc = (float*)pxbc;
    float* dtb = (float*)pdt;
    float* yb  = (float*)py;
    float* Gb  = (float*)pG;
    float* spb = (float*)psp;
    float* acb = (float*)pac;
    __half* uh  = (__half*)puh;
    __half* wih = (__half*)pwih;
    __half* nmh = (__half*)pnmh;
    __half* woh = (__half*)pwoh;

    cudaFuncSetAttribute(gemm_mma_kernel, cudaFuncAttributeMaxDynamicSharedMemorySize,
                         mg::SMEM_BYTES);
    cudaFuncSetAttribute(ssd_pass3, cudaFuncAttributeMaxDynamicSharedMemorySize,
                         (int)sizeof(P3S));

    // fp32 -> fp16 pre-swizzled tile converts
    cvt_swz_kernel<<<(cfg::BL / 128) * (cfg::D_MODEL / 64), 256>>>(
        u, uh, cfg::BL, cfg::D_MODEL);
    cvt_swz_kernel<<<(cfg::N1_PAD / 128) * (cfg::D_MODEL / 64), 256>>>(
        W_in, wih, cfg::D_IN_PROJ, cfg::D_MODEL);
    cvt_swz_kernel<<<(cfg::D_MODEL / 128) * (cfg::D_INNER / 64), 256>>>(
        W_out, woh, cfg::D_MODEL, cfg::D_INNER);

    // GEMM1: zx = u @ W_in^T  (block 128x256)
    {
        dim3 grid(cfg::N1_PAD / 256, cfg::BL / 128);
        gemm_mma_kernel<<<grid, 256, mg::SMEM_BYTES>>>(uh, wih, zx,
                                                       cfg::BL, cfg::D_IN_PROJ, cfg::D_MODEL);
    }
    // fused conv+silu and dt softplus
    conv_dt_kernel<<<fc::NCONV + fc::NDT, 256>>>(zx, conv_w, conv_b, dt_bias, xbc, dtb);
    // SSD: 3 passes
    ssd_pass1<<<cfg::NBH * cfg::NCHUNK, 256>>>(xbc, dtb, A_log, Gb, acb);
    ssd_pass2<<<cfg::NBH * 4, 256>>>(Gb, acb, spb);
    ssd_pass3<<<cfg::NBH * cfg::NCHUNK, 256, sizeof(P3S)>>>(
        xbc, dtb, D_param, spb, acb, yb);
    // gate + rmsnorm -> fp16 (swizzled tiles)
    gate_norm_kernel<<<cfg::BL, 256>>>(yb, zx, norm_w, nmh);
    // GEMM2: out = nm @ W_out^T  (block 128x256)
    {
        dim3 grid(cfg::D_MODEL / 256, cfg::BL / 128);
        gemm_mma_kernel<<<grid, 256, mg::SMEM_BYTES>>>(nmh, woh, out,
                                                       cfg::BL, cfg::D_MODEL, cfg::D_INNER);
    }
}

// round 13
// speedup vs baseline: 1.0563x; 1.0563x over previous
#include <cuda_runtime.h>
#include <cuda_fp16.h>
#include <math.h>
#include <stdint.h>

// ---------------------------------------------------------------------------
// Problem constants (Mamba2 block, B=2, L=4096)
// ---------------------------------------------------------------------------
namespace cfg {
constexpr int D_MODEL   = 2048;
constexpr int D_INNER   = 4096;
constexpr int D_STATE   = 64;
constexpr int D_CONV    = 4;
constexpr int NHEADS    = 64;
constexpr int HEADDIM   = 64;
constexpr int D_XBC     = D_INNER + 2 * D_STATE;              // 4224
constexpr int D_IN_PROJ = 2 * D_INNER + 2 * D_STATE + NHEADS; // 8384
constexpr int LSEQ      = 4096;
constexpr int BATCH     = 2;
constexpr int BL        = BATCH * LSEQ;                       // 8192
constexpr int CHUNK     = 64;
constexpr int NCHUNK    = LSEQ / CHUNK;                       // 64
constexpr int NBH       = BATCH * NHEADS;                     // 128
constexpr int N1_PAD    = 8448;
}

// ---------------------------------------------------------------------------
// Scratch (allocation-free: __device__ globals; zero-init at load)
// ---------------------------------------------------------------------------
__device__ float  g_zx [(size_t)cfg::BL * cfg::D_IN_PROJ];
__device__ __half g_xbc[(size_t)cfg::BL * cfg::D_XBC];       // fp16 conv output
__device__ float  g_dt [(size_t)cfg::BL * cfg::NHEADS];
__device__ float  g_y  [(size_t)cfg::BL * cfg::D_INNER];

// SSD intermediates (fp16 storage; fp32 accumulate in registers)
__device__ __half g_G    [(size_t)cfg::NBH * cfg::NCHUNK * 64 * 64];
__device__ __half g_sprev[(size_t)cfg::NBH * cfg::NCHUNK * 64 * 64];
__device__ float  g_acum [(size_t)cfg::NBH * cfg::NCHUNK * 64];

// fp16 operands, PRE-SWIZZLED 16KB tiles (128 rows x 64 cols)
__device__ __half g_uh [(size_t)cfg::BL * cfg::D_MODEL];
__device__ __half g_wih[(size_t)cfg::N1_PAD * cfg::D_MODEL];
__device__ __half g_nmh[(size_t)cfg::BL * cfg::D_INNER];
__device__ __half g_woh[(size_t)cfg::D_MODEL * cfg::D_INNER];

// ---------------------------------------------------------------------------
// PTX helpers
// ---------------------------------------------------------------------------
__device__ __forceinline__ uint32_t smem_u32(const void* p) {
    uint32_t a;
    asm("{ .reg .u64 t; cvta.to.shared.u64 t, %1; cvt.u32.u64 %0, t; }"
        : "=r"(a) : "l"(p));
    return a;
}
__device__ __forceinline__ void ldsm4(uint32_t r[4], uint32_t addr) {
    asm volatile("ldmatrix.sync.aligned.m8n8.x4.shared.b16 {%0,%1,%2,%3}, [%4];"
                 : "=r"(r[0]), "=r"(r[1]), "=r"(r[2]), "=r"(r[3]) : "r"(addr));
}
__device__ __forceinline__ void ldsm2(uint32_t r[2], uint32_t addr) {
    asm volatile("ldmatrix.sync.aligned.m8n8.x2.shared.b16 {%0,%1}, [%2];"
                 : "=r"(r[0]), "=r"(r[1]) : "r"(addr));
}
__device__ __forceinline__ void mma16816h(float c[4], const uint32_t a[4],
                                          uint32_t b0, uint32_t b1) {
    asm volatile(
        "mma.sync.aligned.m16n8k16.row.col.f32.f16.f16.f32 "
        "{%0,%1,%2,%3}, {%4,%5,%6,%7}, {%8,%9}, {%0,%1,%2,%3};"
        : "+f"(c[0]), "+f"(c[1]), "+f"(c[2]), "+f"(c[3])
        : "r"(a[0]), "r"(a[1]), "r"(a[2]), "r"(a[3]), "r"(b0), "r"(b1));
}
__device__ __forceinline__ void bulk_cp(uint32_t dst, const void* src,
                                        uint32_t bytes, uint32_t mbar) {
    asm volatile(
        "cp.async.bulk.shared::cta.global.mbarrier::complete_tx::bytes "
        "[%0], [%1], %2, [%3];"
        :: "r"(dst), "l"(src), "r"(bytes), "r"(mbar) : "memory");
}
#define MBARRIER_INIT(addr, cnt) \
    asm volatile("mbarrier.init.shared.b64 [%0], %1;" :: "r"(addr), "r"(cnt) : "memory")
#define MBARRIER_EXPECT_TX(addr, bytes) \
    asm volatile("mbarrier.arrive.expect_tx.shared.b64 _, [%0], %1;" \
                 :: "r"(addr), "r"(bytes) : "memory")
#define MBARRIER_WAIT_PARITY(addr, par) do {                                      \
    uint32_t _m = (addr); uint32_t _p = (par); uint32_t _done;                    \
    asm volatile("{\n\t.reg .pred p;\n\t"                                         \
        "mbarrier.try_wait.parity.acquire.cta.shared::cta.b64 p, [%1], %2;\n\t"   \
        "selp.b32 %0, 1, 0, p;\n\t}" : "=r"(_done) : "r"(_m), "r"(_p) : "memory");\
    if (!_done) {                                                                 \
        asm volatile("{\n\t.reg .pred P1;\n\t"                                    \
        "WL_%=:\n\t"                                                              \
        "mbarrier.try_wait.parity.acquire.cta.shared::cta.b64 P1, [%0], %1, 0x989680;\n\t" \
        "@P1 bra.uni WD_%=;\n\tbra.uni WL_%=;\n\tWD_%=:\n\t}"                     \
        :: "r"(_m), "r"(_p) : "memory");                                          \
    } } while (0)

__device__ __forceinline__ int swz_idx(int row, int col) {
    return row * 64 + (((col >> 3) ^ (row & 7)) << 3) + (col & 7);
}

// ---------------------------------------------------------------------------
// HMMA fp16 GEMM on pre-swizzled tiles — EXACT R11 config (128x128x64,
// 8 warps 2x4, warp tile 64x32, 2 CTA/SM, 3-slot bulk-copy pipeline).
// ---------------------------------------------------------------------------
namespace mg {
constexpr int KT    = 64;
constexpr int TILEB = 128 * KT * 2;          // 16384 B
constexpr int STAGE = 2 * TILEB;             // 32768 B
constexpr int STAGES = 3;
constexpr int MBAR_OFF = STAGES * STAGE;     // 98304
constexpr int SMEM_BYTES = MBAR_OFF + 64;
}

__global__ __launch_bounds__(256, 2) void gemm_mma_kernel(
    const __half* __restrict__ At, const __half* __restrict__ Bt,
    float* __restrict__ C, int M, int N, int K)
{
    extern __shared__ char smraw[];
    const uint32_t sb = smem_u32(smraw);
    const int tid  = threadIdx.x;
    const int bm   = blockIdx.y * 128;
    const int bn   = blockIdx.x * 128;
    const int wid  = tid >> 5, lane = tid & 31;
    const int wm   = wid & 1;
    const int wn   = wid >> 1;
    const int NK   = K >> 6;

    const __half* Abase = At + (size_t)blockIdx.y * NK * 8192;
    const __half* Bbase = Bt + (size_t)blockIdx.x * NK * 8192;
    const uint32_t mb = sb + mg::MBAR_OFF;

    if (tid == 0) {
        MBARRIER_INIT(mb,      1u);
        MBARRIER_INIT(mb + 8,  1u);
        MBARRIER_INIT(mb + 16, 1u);
    }
    __syncthreads();

    auto issue = [&](int stage, int kblk) {
        const uint32_t m = mb + stage * 8;
        MBARRIER_EXPECT_TX(m, (uint32_t)mg::STAGE);
        const uint32_t d = sb + stage * mg::STAGE;
        bulk_cp(d,             Abase + (size_t)kblk * 8192, mg::TILEB, m);
        bulk_cp(d + mg::TILEB, Bbase + (size_t)kblk * 8192, mg::TILEB, m);
    };

    float acc[4][4][4];
#pragma unroll
    for (int i = 0; i < 4; i++)
#pragma unroll
        for (int j = 0; j < 4; j++)
#pragma unroll
            for (int q = 0; q < 4; q++) acc[i][j][q] = 0.f;

    if (tid == 0) { issue(0, 0); issue(1, 1); }

    for (int kb = 0; kb < NK; kb++) {
        const int st = kb % mg::STAGES;
        MBARRIER_WAIT_PARITY(mb + st * 8, (uint32_t)((kb / 3) & 1));
        __syncthreads();

        if (kb + 2 < NK && tid == 0)
            issue((kb + 2) % mg::STAGES, kb + 2);

        const uint32_t sA = sb + st * mg::STAGE;
        const uint32_t sB = sA + mg::TILEB;

#pragma unroll
        for (int ks = 0; ks < 4; ks++) {
            uint32_t bf[4][2];
#pragma unroll
            for (int nt = 0; nt < 4; nt++) {
                int nr = wn * 32 + nt * 8 + (lane & 7);
                int g  = 2 * ks + ((lane >> 3) & 1);
                uint32_t off = nr * 128 + (((g ^ (nr & 7))) << 4);
                ldsm2(bf[nt], sB + off);
            }
            uint32_t a[4][4];
#pragma unroll
            for (int mt = 0; mt < 4; mt++) {
                int ar = wm * 64 + mt * 16 + (lane & 15);
                int g  = 2 * ks + (lane >> 4);
                uint32_t off = ar * 128 + (((g ^ (ar & 7))) << 4);
                ldsm4(a[mt], sA + off);
            }
#pragma unroll
            for (int mt = 0; mt < 4; mt++)
#pragma unroll
                for (int nt = 0; nt < 4; nt++)
                    mma16816h(acc[mt][nt], a[mt], bf[nt][0], bf[nt][1]);
        }
    }

#pragma unroll
    for (int mt = 0; mt < 4; mt++) {
#pragma unroll
        for (int nt = 0; nt < 4; nt++) {
            int row = bm + wm * 64 + mt * 16 + (lane >> 2);
            int col = bn + wn * 32 + nt * 8 + (lane & 3) * 2;
            if (col < N) {
                *(float2*)(C + (size_t)row * N + col) =
                    make_float2(acc[mt][nt][0], acc[mt][nt][1]);
                *(float2*)(C + (size_t)(row + 8) * N + col) =
                    make_float2(acc[mt][nt][2], acc[mt][nt][3]);
            }
        }
    }
}

// ---------------------------------------------------------------------------
// fp32 row-major -> fp16 pre-swizzled 16KB tiles
// ---------------------------------------------------------------------------
__global__ __launch_bounds__(256) void cvt_swz_kernel(
    const float* __restrict__ src, __half* __restrict__ dst, int Mreal, int K)
{
    const int NKt = K >> 6;
    const int tile = blockIdx.x;
    const int tm = tile / NKt, tk = tile % NKt;
    __half* d = dst + (size_t)tile * 8192;
#pragma unroll
    for (int it = 0; it < 4; it++) {
        int id = it * 256 + threadIdx.x;
        int r  = id >> 3, g = id & 7;
        int grow = tm * 128 + r;
        uint32_t off = (uint32_t)(r * 64 + ((g ^ (r & 7)) << 3));
        uint4 pk;
        if (grow < Mreal) {
            const float* s = src + (size_t)grow * K + tk * 64 + g * 8;
            float4 v0 = *(const float4*)s;
            float4 v1 = *(const float4*)(s + 4);
            __half2 h0 = __floats2half2_rn(v0.x, v0.y);
            __half2 h1 = __floats2half2_rn(v0.z, v0.w);
            __half2 h2 = __floats2half2_rn(v1.x, v1.y);
            __half2 h3 = __floats2half2_rn(v1.z, v1.w);
            pk.x = *(uint32_t*)&h0; pk.y = *(uint32_t*)&h1;
            pk.z = *(uint32_t*)&h2; pk.w = *(uint32_t*)&h3;
        } else {
            pk = make_uint4(0, 0, 0, 0);
        }
        *(uint4*)(d + off) = pk;
    }
}

// ---------------------------------------------------------------------------
// Fused conv+silu (fp16 output) and dt softplus
// ---------------------------------------------------------------------------
namespace fc {
constexpr int NCONV = (cfg::BL * cfg::D_XBC + 255) / 256;
constexpr int NDT   = (cfg::BL * cfg::NHEADS + 255) / 256;
}

__global__ void conv_dt_kernel(const float* __restrict__ zx,
                               const float* __restrict__ cw,
                               const float* __restrict__ cb,
                               const float* __restrict__ dt_bias,
                               __half* __restrict__ xbc_out,
                               float* __restrict__ dt_out)
{
    int blk = blockIdx.x;
    if (blk < fc::NCONV) {
        int idx = blk * 256 + threadIdx.x;
        if (idx >= cfg::BL * cfg::D_XBC) return;
        int j = idx % cfg::D_XBC;
        int t = idx / cfg::D_XBC;
        int l = t & (cfg::LSEQ - 1);
        int b = t >> 12;
        float v = cb[j];
#pragma unroll
        for (int k = 0; k < cfg::D_CONV; k++) {
            int ls = l + k - (cfg::D_CONV - 1);
            if (ls >= 0)
                v = fmaf(cw[j * cfg::D_CONV + k],
                         zx[(size_t)(b * cfg::LSEQ + ls) * cfg::D_IN_PROJ + cfg::D_INNER + j], v);
        }
        xbc_out[(size_t)t * cfg::D_XBC + j] = __float2half_rn(v / (1.f + expf(-v)));
    } else {
        int idx = (blk - fc::NCONV) * 256 + threadIdx.x;
        if (idx >= cfg::BL * cfg::NHEADS) return;
        int h = idx & 63;
        int t = idx >> 6;
        float x = zx[(size_t)t * cfg::D_IN_PROJ + cfg::D_INNER + cfg::D_XBC + h] + dt_bias[h];
        dt_out[idx] = (x > 20.f) ? x : log1pf(expf(x));
    }
}

// ---------------------------------------------------------------------------
// SSD pass 1 (HMMA, fp16 inputs/outputs)
// ---------------------------------------------------------------------------
__global__ __launch_bounds__(256) void ssd_pass1(
    const __half* __restrict__ xbc, const float* __restrict__ dtg,
    const float* __restrict__ A_log,
    __half* __restrict__ G, float* __restrict__ acum)
{
    __shared__ __half Bw[4096];
    __shared__ __half Xt[4096];
    __shared__ float Acum[64], ws[64], dts[64];
    const int blk = blockIdx.x;
    const int c = blk & 63, bh = blk >> 6;
    const int h = bh & 63, b = bh >> 6;
    const int tid = threadIdx.x;
    const float Aneg = -expf(A_log[h]);
    const int l0g = c * cfg::CHUNK;

    if (tid < 64) {
        const int lane = tid & 31;
        size_t row = (size_t)(b * cfg::LSEQ + l0g + tid);
        float dtv = dtg[row * cfg::NHEADS + h];
        dts[tid] = dtv;
        float v = Aneg * dtv;
#pragma unroll
        for (int o = 1; o < 32; o <<= 1) {
            float n = __shfl_up_sync(0xffffffffu, v, o);
            if (lane >= o) v += n;
        }
        Acum[tid] = v;
    }
    __syncthreads();
    if (tid < 64) {
        float v = Acum[tid] + ((tid >= 32) ? Acum[31] : 0.f);
        Acum[tid] = v;
    }
    __syncthreads();
    if (tid < 64) {
        ws[tid] = expf(Acum[63] - Acum[tid]);
        acum[(size_t)blk * 64 + tid] = Acum[tid];
    }
    __syncthreads();

    for (int idx = tid; idx < 1024; idx += 256) {
        int l = idx >> 4, q4 = (idx & 15) * 4;
        size_t row = (size_t)(b * cfg::LSEQ + l0g + l);
        const __half* xr = xbc + row * cfg::D_XBC;
        float dtv = dts[l], wv = ws[l];
        uint2 xb = *(const uint2*)(xr + h * cfg::HEADDIM + q4);
        uint2 bb = *(const uint2*)(xr + cfg::D_INNER + q4);
        float2 x01 = __half22float2(*(__half2*)&xb.x);
        float2 x23 = __half22float2(*(__half2*)&xb.y);
        float2 b01 = __half22float2(*(__half2*)&bb.x);
        float2 b23 = __half22float2(*(__half2*)&bb.y);
        float xa[4] = {x01.x, x01.y, x23.x, x23.y};
        float ba[4] = {b01.x, b01.y, b23.x, b23.y};
#pragma unroll
        for (int e = 0; e < 4; e++) {
            int p = q4 + e;
            Xt[swz_idx(p, l)] = __float2half_rn(xa[e] * dtv);
            Bw[swz_idx(p, l)] = __float2half_rn(ba[e] * wv);
        }
    }
    __syncthreads();

    const int wid = tid >> 5, lane = tid & 31;
    const int wr = wid & 3, wc = wid >> 2;
    const uint32_t sBw = smem_u32(Bw), sXt = smem_u32(Xt);
    float acc[4][4];
#pragma unroll
    for (int i = 0; i < 4; i++)
#pragma unroll
        for (int j = 0; j < 4; j++) acc[i][j] = 0.f;

#pragma unroll
    for (int ks = 0; ks < 4; ks++) {
        uint32_t a[4];
        {
            int ar = wr * 16 + (lane & 15);
            int g  = 2 * ks + (lane >> 4);
            ldsm4(a, sBw + ar * 128 + ((g ^ (ar & 7)) << 4));
        }
#pragma unroll
        for (int nt = 0; nt < 4; nt++) {
            uint32_t bb2[2];
            int nr = wc * 32 + nt * 8 + (lane & 7);
            int g  = 2 * ks + ((lane >> 3) & 1);
            ldsm2(bb2, sXt + nr * 128 + ((g ^ (nr & 7)) << 4));
            mma16816h(acc[nt], a, bb2[0], bb2[1]);
        }
    }

    __half* gout = G + (size_t)blk * 4096;
    const int n0 = wr * 16 + (lane >> 2);
#pragma unroll
    for (int nt = 0; nt < 4; nt++) {
        int p = wc * 32 + nt * 8 + (lane & 3) * 2;
        __half2 v0 = __floats2half2_rn(acc[nt][0], acc[nt][1]);
        __half2 v1 = __floats2half2_rn(acc[nt][2], acc[nt][3]);
        *(__half2*)(gout + n0 * 64 + p)       = v0;
        *(__half2*)(gout + (n0 + 8) * 64 + p) = v1;
    }
}

// ---------------------------------------------------------------------------
// SSD pass 2: chunk-state scan; fp16 G in, fp16 sprev out, fp32 accumulate
// ---------------------------------------------------------------------------
__global__ __launch_bounds__(256) void ssd_pass2(
    const __half* __restrict__ G, const float* __restrict__ acum,
    __half* __restrict__ sprev)
{
    __shared__ float eAc[cfg::NCHUNK];
    const int bh    = blockIdx.x >> 2;
    const int slice = blockIdx.x & 3;
    const int tid   = threadIdx.x;
    if (tid < cfg::NCHUNK)
        eAc[tid] = expf(acum[((size_t)bh * cfg::NCHUNK + tid) * 64 + 63]);
    __syncthreads();

    const int f4 = slice * 256 + tid;
    float4 S = make_float4(0.f, 0.f, 0.f, 0.f);
    const size_t bhbase = (size_t)bh * cfg::NCHUNK * 4096;
    for (int c = 0; c < cfg::NCHUNK; c++) {
        const size_t base = bhbase + (size_t)c * 4096 + f4 * 4;
        uint2 sp;
        __half2 s01 = __floats2half2_rn(S.x, S.y);
        __half2 s23 = __floats2half2_rn(S.z, S.w);
        sp.x = *(uint32_t*)&s01; sp.y = *(uint32_t*)&s23;
        *(uint2*)(sprev + base) = sp;
        uint2 gp = *(const uint2*)(G + base);
        float2 g01 = __half22float2(*(__half2*)&gp.x);
        float2 g23 = __half22float2(*(__half2*)&gp.y);
        float ea = eAc[c];
        S.x = fmaf(ea, S.x, g01.x);
        S.y = fmaf(ea, S.y, g01.y);
        S.z = fmaf(ea, S.z, g23.x);
        S.w = fmaf(ea, S.w, g23.y);
    }
}

// ---------------------------------------------------------------------------
// SSD pass 3 (HMMA, fp16 inputs)
// ---------------------------------------------------------------------------
struct P3S {
    __half Ct [4096];
    __half Bt [4096];
    __half Xt [4096];
    __half Spt[4096];
    __half W2 [4096];
    float  Xraw[4096];
    float  Acum[64], eA[64], dts[64];
};

__global__ __launch_bounds__(256) void ssd_pass3(
    const __half* __restrict__ xbc, const float* __restrict__ dtg,
    const float* __restrict__ D_param,
    const __half* __restrict__ sprev, const float* __restrict__ acum,
    float* __restrict__ y)
{
    extern __shared__ char smraw[];
    P3S& sm = *reinterpret_cast<P3S*>(smraw);
    const int blk = blockIdx.x;
    const int c = blk & 63, bh = blk >> 6;
    const int h = bh & 63, b = bh >> 6;
    const int tid = threadIdx.x;
    const float Dh = D_param[h];
    const int l0g = c * cfg::CHUNK;

    if (tid < 64) {
        size_t row = (size_t)(b * cfg::LSEQ + l0g + tid);
        sm.dts[tid] = dtg[row * cfg::NHEADS + h];
        float a = acum[(size_t)blk * 64 + tid];
        sm.Acum[tid] = a;
        sm.eA[tid]   = expf(a);
    }
    __syncthreads();

    const __half* spin = sprev + (size_t)blk * 4096;
    for (int idx = tid; idx < 1024; idx += 256) {
        int r = idx >> 4, q4 = (idx & 15) * 4;
        size_t grow = (size_t)(b * cfg::LSEQ + l0g + r);
        const __half* xr = xbc + grow * cfg::D_XBC;
        float dtv = sm.dts[r];
        uint2 xb = *(const uint2*)(xr + h * cfg::HEADDIM + q4);
        uint2 bb = *(const uint2*)(xr + cfg::D_INNER + q4);
        uint2 cb2 = *(const uint2*)(xr + cfg::D_INNER + cfg::D_STATE + q4);
        uint2 sp = *(const uint2*)(spin + r * 64 + q4);

        // Bt/Ct: already fp16, direct swizzled copy (q4 is 4-aligned within 8-granule)
        int ci = swz_idx(r, q4);
        *(uint2*)&sm.Ct[ci] = cb2;
        *(uint2*)&sm.Bt[ci] = bb;

        float2 x01 = __half22float2(*(__half2*)&xb.x);
        float2 x23 = __half22float2(*(__half2*)&xb.y);
        float xa[4] = {x01.x, x01.y, x23.x, x23.y};
        *(float4*)&sm.Xraw[r * 64 + q4] = make_float4(xa[0], xa[1], xa[2], xa[3]);

        const __half* spv = (const __half*)&sp;
#pragma unroll
        for (int e = 0; e < 4; e++) {
            int p = q4 + e;
            sm.Xt [swz_idx(p, r)] = __float2half_rn(xa[e] * dtv);
            sm.Spt[swz_idx(p, r)] = spv[e];
        }
    }
    __syncthreads();

    const int wid = tid >> 5, lane = tid & 31;
    const int wr = wid & 3, wc = wid >> 2;
    const uint32_t sCt = smem_u32(sm.Ct),  sBt = smem_u32(sm.Bt);
    const uint32_t sXt = smem_u32(sm.Xt),  sSp = smem_u32(sm.Spt);
    const uint32_t sW2 = smem_u32(sm.W2);
    const int l0 = wr * 16 + (lane >> 2);

    {
        float accw[4][4];
#pragma unroll
        for (int i = 0; i < 4; i++)
#pragma unroll
            for (int j = 0; j < 4; j++) accw[i][j] = 0.f;
#pragma unroll
        for (int ks = 0; ks < 4; ks++) {
            uint32_t a[4];
            int ar = wr * 16 + (lane & 15);
            int ga = 2 * ks + (lane >> 4);
            ldsm4(a, sCt + ar * 128 + ((ga ^ (ar & 7)) << 4));
#pragma unroll
            for (int nt = 0; nt < 4; nt++) {
                uint32_t bb2[2];
                int sr = wc * 32 + nt * 8 + (lane & 7);
                int gb = 2 * ks + ((lane >> 3) & 1);
                ldsm2(bb2, sBt + sr * 128 + ((gb ^ (sr & 7)) << 4));
                mma16816h(accw[nt], a, bb2[0], bb2[1]);
            }
        }
        float A0 = sm.Acum[l0], A1 = sm.Acum[l0 + 8];
#pragma unroll
        for (int nt = 0; nt < 4; nt++) {
            int s0 = wc * 32 + nt * 8 + (lane & 3) * 2;
            float As0 = sm.Acum[s0], As1 = sm.Acum[s0 + 1];
            float w00 = (s0     <= l0) ? expf(A0 - As0) : 0.f;
            float w01 = (s0 + 1 <= l0) ? expf(A0 - As1) : 0.f;
            float w10 = (s0     <= l0 + 8) ? expf(A1 - As0) : 0.f;
            float w11 = (s0 + 1 <= l0 + 8) ? expf(A1 - As1) : 0.f;
            __half2 h0 = __floats2half2_rn(accw[nt][0] * w00, accw[nt][1] * w01);
            __half2 h1 = __floats2half2_rn(accw[nt][2] * w10, accw[nt][3] * w11);
            *(uint32_t*)&sm.W2[swz_idx(l0,     s0)] = *(uint32_t*)&h0;
            *(uint32_t*)&sm.W2[swz_idx(l0 + 8, s0)] = *(uint32_t*)&h1;
        }
    }
    __syncthreads();

    float accd[4][4], acco[4][4];
#pragma unroll
    for (int i = 0; i < 4; i++)
#pragma unroll
        for (int j = 0; j < 4; j++) { accd[i][j] = 0.f; acco[i][j] = 0.f; }

#pragma unroll
    for (int ks = 0; ks < 4; ks++) {
        uint32_t a[4];
        int ar = wr * 16 + (lane & 15);
        int ga = 2 * ks + (lane >> 4);
        ldsm4(a, sW2 + ar * 128 + ((ga ^ (ar & 7)) << 4));
#pragma unroll
        for (int nt = 0; nt < 4; nt++) {
            uint32_t bb2[2];
            int nr = wc * 32 + nt * 8 + (lane & 7);
            int gb = 2 * ks + ((lane >> 3) & 1);
            ldsm2(bb2, sXt + nr * 128 + ((gb ^ (nr & 7)) << 4));
            mma16816h(accd[nt], a, bb2[0], bb2[1]);
        }
    }
#pragma unroll
    for (int ks = 0; ks < 4; ks++) {
        uint32_t a[4];
        int ar = wr * 16 + (lane & 15);
        int ga = 2 * ks + (lane >> 4);
        ldsm4(a, sCt + ar * 128 + ((ga ^ (ar & 7)) << 4));
#pragma unroll
        for (int nt = 0; nt < 4; nt++) {
            uint32_t bb2[2];
            int nr = wc * 32 + nt * 8 + (lane & 7);
            int gb = 2 * ks + ((lane >> 3) & 1);
            ldsm2(bb2, sSp + nr * 128 + ((gb ^ (nr & 7)) << 4));
            mma16816h(acco[nt], a, bb2[0], bb2[1]);
        }
    }

    const float eA0 = sm.eA[l0], eA1 = sm.eA[l0 + 8];
    const size_t row0 = (size_t)(b * cfg::LSEQ + l0g + l0);
#pragma unroll
    for (int nt = 0; nt < 4; nt++) {
        int p = wc * 32 + nt * 8 + (lane & 3) * 2;
        float x00 = sm.Xraw[l0 * 64 + p],      x01 = sm.Xraw[l0 * 64 + p + 1];
        float x10 = sm.Xraw[(l0 + 8) * 64 + p], x11 = sm.Xraw[(l0 + 8) * 64 + p + 1];
        float2 v0 = make_float2(accd[nt][0] + eA0 * acco[nt][0] + Dh * x00,
                                accd[nt][1] + eA0 * acco[nt][1] + Dh * x01);
        float2 v1 = make_float2(accd[nt][2] + eA1 * acco[nt][2] + Dh * x10,
                                accd[nt][3] + eA1 * acco[nt][3] + Dh * x11);
        *(float2*)(y + row0 * cfg::D_INNER + h * cfg::HEADDIM + p)       = v0;
        *(float2*)(y + (row0 + 8) * cfg::D_INNER + h * cfg::HEADDIM + p) = v1;
    }
}

// ---------------------------------------------------------------------------
// gate + RMSNorm -> fp16 pre-swizzled tiles (unchanged)
// ---------------------------------------------------------------------------
__global__ __launch_bounds__(256) void gate_norm_kernel(
    const float* __restrict__ y, const float* __restrict__ zx,
    const float* __restrict__ nw, __half* __restrict__ nmh)
{
    __shared__ float gbuf[cfg::D_INNER];
    __shared__ float red[8];
    const int t = blockIdx.x;
    const int tid = threadIdx.x;
    const float* yr = y + (size_t)t * cfg::D_INNER;
    const float* zr = zx + (size_t)t * cfg::D_IN_PROJ;

    float ss = 0.f;
    for (int i = tid; i < cfg::D_INNER; i += 256) {
        float zv = zr[i];
        float gv = yr[i] * (zv / (1.f + expf(-zv)));
        gbuf[i] = gv;
        ss = fmaf(gv, gv, ss);
    }
#pragma unroll
    for (int o = 16; o; o >>= 1) ss += __shfl_xor_sync(0xffffffffu, ss, o);
    if ((tid & 31) == 0) red[tid >> 5] = ss;
    __syncthreads();
    if (tid < 32) {
        float v = (tid < 8) ? red[tid] : 0.f;
#pragma unroll
        for (int o = 4; o; o >>= 1) v += __shfl_xor_sync(0xffffffffu, v, o);
        if (tid == 0) red[0] = v;
    }
    __syncthreads();
    const float scale = rsqrtf(red[0] * (1.f / cfg::D_INNER) + 1e-5f);
    const int tm = t >> 7, r = t & 127;
    const size_t tmbase = (size_t)tm * (cfg::D_INNER / 64) * 8192;
    const uint32_t rx = (uint32_t)(r & 7);
    for (int i = tid; i < cfg::D_INNER; i += 256) {
        float val = gbuf[i] * scale * nw[i];
        int tk = i >> 6, g = (i >> 3) & 7, e = i & 7;
        size_t off = tmbase + (size_t)tk * 8192 + r * 64 + ((g ^ rx) << 3) + e;
        nmh[off] = __float2half_rn(val);
    }
}

// ---------------------------------------------------------------------------
// Host launch
// ---------------------------------------------------------------------------
extern "C" void kernel_launch(void* const* d_in, const int* in_sizes, int n_in,
                              void* d_out, int out_size)
{
    (void)in_sizes; (void)n_in; (void)out_size;
    const float* u       = (const float*)d_in[0];
    const float* W_in    = (const float*)d_in[1];
    const float* conv_w  = (const float*)d_in[2];
    const float* conv_b  = (const float*)d_in[3];
    const float* dt_bias = (const float*)d_in[4];
    const float* A_log   = (const float*)d_in[5];
    const float* D_param = (const float*)d_in[6];
    const float* norm_w  = (const float*)d_in[7];
    const float* W_out   = (const float*)d_in[8];
    float* out = (float*)d_out;

    void *pzx, *pxbc, *pdt, *py, *pG, *psp, *pac;
    void *puh, *pwih, *pnmh, *pwoh;
    cudaGetSymbolAddress(&pzx,  g_zx);
    cudaGetSymbolAddress(&pxbc, g_xbc);
    cudaGetSymbolAddress(&pdt,  g_dt);
    cudaGetSymbolAddress(&py,   g_y);
    cudaGetSymbolAddress(&pG,   g_G);
    cudaGetSymbolAddress(&psp,  g_sprev);
    cudaGetSymbolAddress(&pac,  g_acum);
    cudaGetSymbolAddress(&puh,  g_uh);
    cudaGetSymbolAddress(&pwih, g_wih);
    cudaGetSymbolAddress(&pnmh, g_nmh);
    cudaGetSymbolAddress(&pwoh, g_woh);
    float*  zx  = (float*)pzx;
    __half* xbc = (__half*)pxbc;
    float*  dtb = (float*)pdt;
    float*  yb  = (float*)py;
    __half* Gb  = (__half*)pG;
    __half* spb = (__half*)psp;
    float*  acb = (float*)pac;
    __half* uh  = (__half*)puh;
    __half* wih = (__half*)pwih;
    __half* nmh = (__half*)pnmh;
    __half* woh = (__half*)pwoh;

    cudaFuncSetAttribute(gemm_mma_kernel, cudaFuncAttributeMaxDynamicSharedMemorySize,
                         mg::SMEM_BYTES);
    cudaFuncSetAttribute(ssd_pass3, cudaFuncAttributeMaxDynamicSharedMemorySize,
                         (int)sizeof(P3S));

    // fp32 -> fp16 pre-swizzled tile converts
    cvt_swz_kernel<<<(cfg::BL / 128) * (cfg::D_MODEL / 64), 256>>>(
        u, uh, cfg::BL, cfg::D_MODEL);
    cvt_swz_kernel<<<(cfg::N1_PAD / 128) * (cfg::D_MODEL / 64), 256>>>(
        W_in, wih, cfg::D_IN_PROJ, cfg::D_MODEL);
    cvt_swz_kernel<<<(cfg::D_MODEL / 128) * (cfg::D_INNER / 64), 256>>>(
        W_out, woh, cfg::D_MODEL, cfg::D_INNER);

    // GEMM1: zx = u @ W_in^T  (R11 config)
    {
        dim3 grid(cfg::N1_PAD / 128, cfg::BL / 128);
        gemm_mma_kernel<<<grid, 256, mg::SMEM_BYTES>>>(uh, wih, zx,
                                                       cfg::BL, cfg::D_IN_PROJ, cfg::D_MODEL);
    }
    // fused conv+silu (fp16 out) and dt softplus
    conv_dt_kernel<<<fc::NCONV + fc::NDT, 256>>>(zx, conv_w, conv_b, dt_bias, xbc, dtb);
    // SSD: 3 passes (fp16 intermediates)
    ssd_pass1<<<cfg::NBH * cfg::NCHUNK, 256>>>(xbc, dtb, A_log, Gb, acb);
    ssd_pass2<<<cfg::NBH * 4, 256>>>(Gb, acb, spb);
    ssd_pass3<<<cfg::NBH * cfg::NCHUNK, 256, sizeof(P3S)>>>(
        xbc, dtb, D_param, spb, acb, yb);
    // gate + rmsnorm -> fp16 (swizzled tiles)
    gate_norm_kernel<<<cfg::BL, 256>>>(yb, zx, norm_w, nmh);
    // GEMM2: out = nm @ W_out^T  (R11 config)
    {
        dim3 grid(cfg::D_MODEL / 128, cfg::BL / 128);
        gemm_mma_kernel<<<grid, 256, mg::SMEM_BYTES>>>(nmh, woh, out,
                                                       cfg::BL, cfg::D_MODEL, cfg::D_INNER);
    }
}

// round 14
// speedup vs baseline: 1.1717x; 1.1092x over previous
#include <cuda_runtime.h>
#include <cuda_fp16.h>
#include <math.h>
#include <stdint.h>

// ---------------------------------------------------------------------------
// Problem constants (Mamba2 block, B=2, L=4096)
// ---------------------------------------------------------------------------
namespace cfg {
constexpr int D_MODEL   = 2048;
constexpr int D_INNER   = 4096;
constexpr int D_STATE   = 64;
constexpr int D_CONV    = 4;
constexpr int NHEADS    = 64;
constexpr int HEADDIM   = 64;
constexpr int D_XBC     = D_INNER + 2 * D_STATE;              // 4224
constexpr int D_IN_PROJ = 2 * D_INNER + 2 * D_STATE + NHEADS; // 8384
constexpr int LSEQ      = 4096;
constexpr int BATCH     = 2;
constexpr int BL        = BATCH * LSEQ;                       // 8192
constexpr int CHUNK     = 64;
constexpr int NCHUNK    = LSEQ / CHUNK;                       // 64
constexpr int NBH       = BATCH * NHEADS;                     // 128
constexpr int N1_PAD    = 8448;
}

// ---------------------------------------------------------------------------
// Scratch (allocation-free: __device__ globals; zero-init at load)
// ---------------------------------------------------------------------------
__device__ float  g_zx [(size_t)cfg::BL * cfg::D_IN_PROJ];
__device__ __half g_xbc[(size_t)cfg::BL * cfg::D_XBC];
__device__ float  g_dt [(size_t)cfg::BL * cfg::NHEADS];
__device__ __half g_y  [(size_t)cfg::BL * cfg::D_INNER];     // fp16 SSD output

// SSD intermediates (fp16 storage; fp32 accumulate in registers)
__device__ __half g_G    [(size_t)cfg::NBH * cfg::NCHUNK * 64 * 64];
__device__ __half g_sprev[(size_t)cfg::NBH * cfg::NCHUNK * 64 * 64];
__device__ float  g_acum [(size_t)cfg::NBH * cfg::NCHUNK * 64];

// fp16 operands, PRE-SWIZZLED 16KB tiles (128 rows x 64 cols)
__device__ __half g_uh [(size_t)cfg::BL * cfg::D_MODEL];
__device__ __half g_wih[(size_t)cfg::N1_PAD * cfg::D_MODEL];
__device__ __half g_nmh[(size_t)cfg::BL * cfg::D_INNER];
__device__ __half g_woh[(size_t)cfg::D_MODEL * cfg::D_INNER];

// ---------------------------------------------------------------------------
// PTX helpers
// ---------------------------------------------------------------------------
__device__ __forceinline__ uint32_t smem_u32(const void* p) {
    uint32_t a;
    asm("{ .reg .u64 t; cvta.to.shared.u64 t, %1; cvt.u32.u64 %0, t; }"
        : "=r"(a) : "l"(p));
    return a;
}
__device__ __forceinline__ void ldsm4(uint32_t r[4], uint32_t addr) {
    asm volatile("ldmatrix.sync.aligned.m8n8.x4.shared.b16 {%0,%1,%2,%3}, [%4];"
                 : "=r"(r[0]), "=r"(r[1]), "=r"(r[2]), "=r"(r[3]) : "r"(addr));
}
__device__ __forceinline__ void ldsm2(uint32_t r[2], uint32_t addr) {
    asm volatile("ldmatrix.sync.aligned.m8n8.x2.shared.b16 {%0,%1}, [%2];"
                 : "=r"(r[0]), "=r"(r[1]) : "r"(addr));
}
__device__ __forceinline__ void mma16816h(float c[4], const uint32_t a[4],
                                          uint32_t b0, uint32_t b1) {
    asm volatile(
        "mma.sync.aligned.m16n8k16.row.col.f32.f16.f16.f32 "
        "{%0,%1,%2,%3}, {%4,%5,%6,%7}, {%8,%9}, {%0,%1,%2,%3};"
        : "+f"(c[0]), "+f"(c[1]), "+f"(c[2]), "+f"(c[3])
        : "r"(a[0]), "r"(a[1]), "r"(a[2]), "r"(a[3]), "r"(b0), "r"(b1));
}
__device__ __forceinline__ void bulk_cp(uint32_t dst, const void* src,
                                        uint32_t bytes, uint32_t mbar) {
    asm volatile(
        "cp.async.bulk.shared::cta.global.mbarrier::complete_tx::bytes "
        "[%0], [%1], %2, [%3];"
        :: "r"(dst), "l"(src), "r"(bytes), "r"(mbar) : "memory");
}
#define MBARRIER_INIT(addr, cnt) \
    asm volatile("mbarrier.init.shared.b64 [%0], %1;" :: "r"(addr), "r"(cnt) : "memory")
#define MBARRIER_EXPECT_TX(addr, bytes) \
    asm volatile("mbarrier.arrive.expect_tx.shared.b64 _, [%0], %1;" \
                 :: "r"(addr), "r"(bytes) : "memory")
#define MBARRIER_ARRIVE(addr) \
    asm volatile("mbarrier.arrive.release.cta.shared::cta.b64 _, [%0];" \
                 :: "r"(addr) : "memory")
#define MBARRIER_WAIT_PARITY(addr, par) do {                                      \
    uint32_t _m = (addr); uint32_t _p = (par); uint32_t _done;                    \
    asm volatile("{\n\t.reg .pred p;\n\t"                                         \
        "mbarrier.try_wait.parity.acquire.cta.shared::cta.b64 p, [%1], %2;\n\t"   \
        "selp.b32 %0, 1, 0, p;\n\t}" : "=r"(_done) : "r"(_m), "r"(_p) : "memory");\
    if (!_done) {                                                                 \
        asm volatile("{\n\t.reg .pred P1;\n\t"                                    \
        "WL_%=:\n\t"                                                              \
        "mbarrier.try_wait.parity.acquire.cta.shared::cta.b64 P1, [%0], %1, 0x989680;\n\t" \
        "@P1 bra.uni WD_%=;\n\tbra.uni WL_%=;\n\tWD_%=:\n\t}"                     \
        :: "r"(_m), "r"(_p) : "memory");                                          \
    } } while (0)

__device__ __forceinline__ int swz_idx(int row, int col) {
    return row * 64 + (((col >> 3) ^ (row & 7)) << 3) + (col & 7);
}

// ---------------------------------------------------------------------------
// HMMA fp16 GEMM, 128x128x64, 2 CTA/SM. WARP-DECOUPLED pipeline:
// full[s] = tx-barrier for bulk-copy completion (as before);
// empty[s] = consumer barrier, count 256 (every thread arrives after reading);
// producer (tid 0) waits empty[s] before re-issuing. NO __syncthreads in loop.
// ---------------------------------------------------------------------------
namespace mg {
constexpr int KT    = 64;
constexpr int TILEB = 128 * KT * 2;          // 16384 B
constexpr int STAGE = 2 * TILEB;             // 32768 B
constexpr int STAGES = 3;
constexpr int MBAR_OFF = STAGES * STAGE;     // 98304; full[3] @ +0..16, empty[3] @ +24..40
constexpr int SMEM_BYTES = MBAR_OFF + 64;
}

__global__ __launch_bounds__(256, 2) void gemm_mma_kernel(
    const __half* __restrict__ At, const __half* __restrict__ Bt,
    float* __restrict__ C, int M, int N, int K)
{
    extern __shared__ char smraw[];
    const uint32_t sb = smem_u32(smraw);
    const int tid  = threadIdx.x;
    const int bm   = blockIdx.y * 128;
    const int bn   = blockIdx.x * 128;
    const int wid  = tid >> 5, lane = tid & 31;
    const int wm   = wid & 1;
    const int wn   = wid >> 1;
    const int NK   = K >> 6;

    const __half* Abase = At + (size_t)blockIdx.y * NK * 8192;
    const __half* Bbase = Bt + (size_t)blockIdx.x * NK * 8192;
    const uint32_t mb = sb + mg::MBAR_OFF;

    if (tid == 0) {
        MBARRIER_INIT(mb,      1u);    // full0
        MBARRIER_INIT(mb + 8,  1u);    // full1
        MBARRIER_INIT(mb + 16, 1u);    // full2
        MBARRIER_INIT(mb + 24, 256u);  // empty0
        MBARRIER_INIT(mb + 32, 256u);  // empty1
        MBARRIER_INIT(mb + 40, 256u);  // empty2
    }
    __syncthreads();

    auto issue = [&](int stage, int kblk) {
        const uint32_t m = mb + stage * 8;
        MBARRIER_EXPECT_TX(m, (uint32_t)mg::STAGE);
        const uint32_t d = sb + stage * mg::STAGE;
        bulk_cp(d,             Abase + (size_t)kblk * 8192, mg::TILEB, m);
        bulk_cp(d + mg::TILEB, Bbase + (size_t)kblk * 8192, mg::TILEB, m);
    };

    float acc[4][4][4];
#pragma unroll
    for (int i = 0; i < 4; i++)
#pragma unroll
        for (int j = 0; j < 4; j++)
#pragma unroll
            for (int q = 0; q < 4; q++) acc[i][j][q] = 0.f;

    if (tid == 0) { issue(0, 0); issue(1, 1); }

    for (int kb = 0; kb < NK; kb++) {
        const int st = kb % mg::STAGES;

        // producer: re-issue stage (kb+2)%3 after its consumers drained
        if (kb + 2 < NK && tid == 0) {
            const int kblk = kb + 2, s2 = kblk % mg::STAGES;
            if (kblk >= 3)
                MBARRIER_WAIT_PARITY(mb + 24 + s2 * 8,
                                     (uint32_t)(((kblk / 3) - 1) & 1));
            issue(s2, kblk);
        }

        // consumer: wait data, compute, release stage (per-thread arrive)
        MBARRIER_WAIT_PARITY(mb + st * 8, (uint32_t)((kb / 3) & 1));

        const uint32_t sA = sb + st * mg::STAGE;
        const uint32_t sB = sA + mg::TILEB;

#pragma unroll
        for (int ks = 0; ks < 4; ks++) {
            uint32_t bf[4][2];
#pragma unroll
            for (int nt = 0; nt < 4; nt++) {
                int nr = wn * 32 + nt * 8 + (lane & 7);
                int g  = 2 * ks + ((lane >> 3) & 1);
                uint32_t off = nr * 128 + (((g ^ (nr & 7))) << 4);
                ldsm2(bf[nt], sB + off);
            }
            uint32_t a[4][4];
#pragma unroll
            for (int mt = 0; mt < 4; mt++) {
                int ar = wm * 64 + mt * 16 + (lane & 15);
                int g  = 2 * ks + (lane >> 4);
                uint32_t off = ar * 128 + (((g ^ (ar & 7))) << 4);
                ldsm4(a[mt], sA + off);
            }
#pragma unroll
            for (int mt = 0; mt < 4; mt++)
#pragma unroll
                for (int nt = 0; nt < 4; nt++)
                    mma16816h(acc[mt][nt], a[mt], bf[nt][0], bf[nt][1]);
        }
        MBARRIER_ARRIVE(mb + 24 + st * 8);
    }

#pragma unroll
    for (int mt = 0; mt < 4; mt++) {
#pragma unroll
        for (int nt = 0; nt < 4; nt++) {
            int row = bm + wm * 64 + mt * 16 + (lane >> 2);
            int col = bn + wn * 32 + nt * 8 + (lane & 3) * 2;
            if (col < N) {
                *(float2*)(C + (size_t)row * N + col) =
                    make_float2(acc[mt][nt][0], acc[mt][nt][1]);
                *(float2*)(C + (size_t)(row + 8) * N + col) =
                    make_float2(acc[mt][nt][2], acc[mt][nt][3]);
            }
        }
    }
}

// ---------------------------------------------------------------------------
// fp32 row-major -> fp16 pre-swizzled 16KB tiles
// ---------------------------------------------------------------------------
__global__ __launch_bounds__(256) void cvt_swz_kernel(
    const float* __restrict__ src, __half* __restrict__ dst, int Mreal, int K)
{
    const int NKt = K >> 6;
    const int tile = blockIdx.x;
    const int tm = tile / NKt, tk = tile % NKt;
    __half* d = dst + (size_t)tile * 8192;
#pragma unroll
    for (int it = 0; it < 4; it++) {
        int id = it * 256 + threadIdx.x;
        int r  = id >> 3, g = id & 7;
        int grow = tm * 128 + r;
        uint32_t off = (uint32_t)(r * 64 + ((g ^ (r & 7)) << 3));
        uint4 pk;
        if (grow < Mreal) {
            const float* s = src + (size_t)grow * K + tk * 64 + g * 8;
            float4 v0 = *(const float4*)s;
            float4 v1 = *(const float4*)(s + 4);
            __half2 h0 = __floats2half2_rn(v0.x, v0.y);
            __half2 h1 = __floats2half2_rn(v0.z, v0.w);
            __half2 h2 = __floats2half2_rn(v1.x, v1.y);
            __half2 h3 = __floats2half2_rn(v1.z, v1.w);
            pk.x = *(uint32_t*)&h0; pk.y = *(uint32_t*)&h1;
            pk.z = *(uint32_t*)&h2; pk.w = *(uint32_t*)&h3;
        } else {
            pk = make_uint4(0, 0, 0, 0);
        }
        *(uint4*)(d + off) = pk;
    }
}

// ---------------------------------------------------------------------------
// Fused conv+silu (fp16 output) and dt softplus
// ---------------------------------------------------------------------------
namespace fc {
constexpr int NCONV = (cfg::BL * cfg::D_XBC + 255) / 256;
constexpr int NDT   = (cfg::BL * cfg::NHEADS + 255) / 256;
}

__global__ void conv_dt_kernel(const float* __restrict__ zx,
                               const float* __restrict__ cw,
                               const float* __restrict__ cb,
                               const float* __restrict__ dt_bias,
                               __half* __restrict__ xbc_out,
                               float* __restrict__ dt_out)
{
    int blk = blockIdx.x;
    if (blk < fc::NCONV) {
        int idx = blk * 256 + threadIdx.x;
        if (idx >= cfg::BL * cfg::D_XBC) return;
        int j = idx % cfg::D_XBC;
        int t = idx / cfg::D_XBC;
        int l = t & (cfg::LSEQ - 1);
        int b = t >> 12;
        float v = cb[j];
#pragma unroll
        for (int k = 0; k < cfg::D_CONV; k++) {
            int ls = l + k - (cfg::D_CONV - 1);
            if (ls >= 0)
                v = fmaf(cw[j * cfg::D_CONV + k],
                         zx[(size_t)(b * cfg::LSEQ + ls) * cfg::D_IN_PROJ + cfg::D_INNER + j], v);
        }
        xbc_out[(size_t)t * cfg::D_XBC + j] = __float2half_rn(v / (1.f + expf(-v)));
    } else {
        int idx = (blk - fc::NCONV) * 256 + threadIdx.x;
        if (idx >= cfg::BL * cfg::NHEADS) return;
        int h = idx & 63;
        int t = idx >> 6;
        float x = zx[(size_t)t * cfg::D_IN_PROJ + cfg::D_INNER + cfg::D_XBC + h] + dt_bias[h];
        dt_out[idx] = (x > 20.f) ? x : log1pf(expf(x));
    }
}

// ---------------------------------------------------------------------------
// SSD pass 1 (HMMA, fp16 in/out)
// ---------------------------------------------------------------------------
__global__ __launch_bounds__(256) void ssd_pass1(
    const __half* __restrict__ xbc, const float* __restrict__ dtg,
    const float* __restrict__ A_log,
    __half* __restrict__ G, float* __restrict__ acum)
{
    __shared__ __half Bw[4096];
    __shared__ __half Xt[4096];
    __shared__ float Acum[64], ws[64], dts[64];
    const int blk = blockIdx.x;
    const int c = blk & 63, bh = blk >> 6;
    const int h = bh & 63, b = bh >> 6;
    const int tid = threadIdx.x;
    const float Aneg = -expf(A_log[h]);
    const int l0g = c * cfg::CHUNK;

    if (tid < 64) {
        const int lane = tid & 31;
        size_t row = (size_t)(b * cfg::LSEQ + l0g + tid);
        float dtv = dtg[row * cfg::NHEADS + h];
        dts[tid] = dtv;
        float v = Aneg * dtv;
#pragma unroll
        for (int o = 1; o < 32; o <<= 1) {
            float n = __shfl_up_sync(0xffffffffu, v, o);
            if (lane >= o) v += n;
        }
        Acum[tid] = v;
    }
    __syncthreads();
    if (tid < 64) {
        float v = Acum[tid] + ((tid >= 32) ? Acum[31] : 0.f);
        Acum[tid] = v;
    }
    __syncthreads();
    if (tid < 64) {
        ws[tid] = expf(Acum[63] - Acum[tid]);
        acum[(size_t)blk * 64 + tid] = Acum[tid];
    }
    __syncthreads();

    for (int idx = tid; idx < 1024; idx += 256) {
        int l = idx >> 4, q4 = (idx & 15) * 4;
        size_t row = (size_t)(b * cfg::LSEQ + l0g + l);
        const __half* xr = xbc + row * cfg::D_XBC;
        float dtv = dts[l], wv = ws[l];
        uint2 xb = *(const uint2*)(xr + h * cfg::HEADDIM + q4);
        uint2 bb = *(const uint2*)(xr + cfg::D_INNER + q4);
        float2 x01 = __half22float2(*(__half2*)&xb.x);
        float2 x23 = __half22float2(*(__half2*)&xb.y);
        float2 b01 = __half22float2(*(__half2*)&bb.x);
        float2 b23 = __half22float2(*(__half2*)&bb.y);
        float xa[4] = {x01.x, x01.y, x23.x, x23.y};
        float ba[4] = {b01.x, b01.y, b23.x, b23.y};
#pragma unroll
        for (int e = 0; e < 4; e++) {
            int p = q4 + e;
            Xt[swz_idx(p, l)] = __float2half_rn(xa[e] * dtv);
            Bw[swz_idx(p, l)] = __float2half_rn(ba[e] * wv);
        }
    }
    __syncthreads();

    const int wid = tid >> 5, lane = tid & 31;
    const int wr = wid & 3, wc = wid >> 2;
    const uint32_t sBw = smem_u32(Bw), sXt = smem_u32(Xt);
    float acc[4][4];
#pragma unroll
    for (int i = 0; i < 4; i++)
#pragma unroll
        for (int j = 0; j < 4; j++) acc[i][j] = 0.f;

#pragma unroll
    for (int ks = 0; ks < 4; ks++) {
        uint32_t a[4];
        {
            int ar = wr * 16 + (lane & 15);
            int g  = 2 * ks + (lane >> 4);
            ldsm4(a, sBw + ar * 128 + ((g ^ (ar & 7)) << 4));
        }
#pragma unroll
        for (int nt = 0; nt < 4; nt++) {
            uint32_t bb2[2];
            int nr = wc * 32 + nt * 8 + (lane & 7);
            int g  = 2 * ks + ((lane >> 3) & 1);
            ldsm2(bb2, sXt + nr * 128 + ((g ^ (nr & 7)) << 4));
            mma16816h(acc[nt], a, bb2[0], bb2[1]);
        }
    }

    __half* gout = G + (size_t)blk * 4096;
    const int n0 = wr * 16 + (lane >> 2);
#pragma unroll
    for (int nt = 0; nt < 4; nt++) {
        int p = wc * 32 + nt * 8 + (lane & 3) * 2;
        __half2 v0 = __floats2half2_rn(acc[nt][0], acc[nt][1]);
        __half2 v1 = __floats2half2_rn(acc[nt][2], acc[nt][3]);
        *(__half2*)(gout + n0 * 64 + p)       = v0;
        *(__half2*)(gout + (n0 + 8) * 64 + p) = v1;
    }
}

// ---------------------------------------------------------------------------
// SSD pass 2 (fp16 storage, fp32 accumulate)
// ---------------------------------------------------------------------------
__global__ __launch_bounds__(256) void ssd_pass2(
    const __half* __restrict__ G, const float* __restrict__ acum,
    __half* __restrict__ sprev)
{
    __shared__ float eAc[cfg::NCHUNK];
    const int bh    = blockIdx.x >> 2;
    const int slice = blockIdx.x & 3;
    const int tid   = threadIdx.x;
    if (tid < cfg::NCHUNK)
        eAc[tid] = expf(acum[((size_t)bh * cfg::NCHUNK + tid) * 64 + 63]);
    __syncthreads();

    const int f4 = slice * 256 + tid;
    float4 S = make_float4(0.f, 0.f, 0.f, 0.f);
    const size_t bhbase = (size_t)bh * cfg::NCHUNK * 4096;
    for (int c = 0; c < cfg::NCHUNK; c++) {
        const size_t base = bhbase + (size_t)c * 4096 + f4 * 4;
        uint2 sp;
        __half2 s01 = __floats2half2_rn(S.x, S.y);
        __half2 s23 = __floats2half2_rn(S.z, S.w);
        sp.x = *(uint32_t*)&s01; sp.y = *(uint32_t*)&s23;
        *(uint2*)(sprev + base) = sp;
        uint2 gp = *(const uint2*)(G + base);
        float2 g01 = __half22float2(*(__half2*)&gp.x);
        float2 g23 = __half22float2(*(__half2*)&gp.y);
        float ea = eAc[c];
        S.x = fmaf(ea, S.x, g01.x);
        S.y = fmaf(ea, S.y, g01.y);
        S.z = fmaf(ea, S.z, g23.x);
        S.w = fmaf(ea, S.w, g23.y);
    }
}

// ---------------------------------------------------------------------------
// SSD pass 3 (HMMA, fp16 in; fp16 y out)
// ---------------------------------------------------------------------------
struct P3S {
    __half Ct [4096];
    __half Bt [4096];
    __half Xt [4096];
    __half Spt[4096];
    __half W2 [4096];
    float  Xraw[4096];
    float  Acum[64], eA[64], dts[64];
};

__global__ __launch_bounds__(256) void ssd_pass3(
    const __half* __restrict__ xbc, const float* __restrict__ dtg,
    const float* __restrict__ D_param,
    const __half* __restrict__ sprev, const float* __restrict__ acum,
    __half* __restrict__ y)
{
    extern __shared__ char smraw[];
    P3S& sm = *reinterpret_cast<P3S*>(smraw);
    const int blk = blockIdx.x;
    const int c = blk & 63, bh = blk >> 6;
    const int h = bh & 63, b = bh >> 6;
    const int tid = threadIdx.x;
    const float Dh = D_param[h];
    const int l0g = c * cfg::CHUNK;

    if (tid < 64) {
        size_t row = (size_t)(b * cfg::LSEQ + l0g + tid);
        sm.dts[tid] = dtg[row * cfg::NHEADS + h];
        float a = acum[(size_t)blk * 64 + tid];
        sm.Acum[tid] = a;
        sm.eA[tid]   = expf(a);
    }
    __syncthreads();

    const __half* spin = sprev + (size_t)blk * 4096;
    for (int idx = tid; idx < 1024; idx += 256) {
        int r = idx >> 4, q4 = (idx & 15) * 4;
        size_t grow = (size_t)(b * cfg::LSEQ + l0g + r);
        const __half* xr = xbc + grow * cfg::D_XBC;
        float dtv = sm.dts[r];
        uint2 xb = *(const uint2*)(xr + h * cfg::HEADDIM + q4);
        uint2 bb = *(const uint2*)(xr + cfg::D_INNER + q4);
        uint2 cb2 = *(const uint2*)(xr + cfg::D_INNER + cfg::D_STATE + q4);
        uint2 sp = *(const uint2*)(spin + r * 64 + q4);

        int ci = swz_idx(r, q4);
        *(uint2*)&sm.Ct[ci] = cb2;
        *(uint2*)&sm.Bt[ci] = bb;

        float2 x01 = __half22float2(*(__half2*)&xb.x);
        float2 x23 = __half22float2(*(__half2*)&xb.y);
        float xa[4] = {x01.x, x01.y, x23.x, x23.y};
        *(float4*)&sm.Xraw[r * 64 + q4] = make_float4(xa[0], xa[1], xa[2], xa[3]);

        const __half* spv = (const __half*)&sp;
#pragma unroll
        for (int e = 0; e < 4; e++) {
            int p = q4 + e;
            sm.Xt [swz_idx(p, r)] = __float2half_rn(xa[e] * dtv);
            sm.Spt[swz_idx(p, r)] = spv[e];
        }
    }
    __syncthreads();

    const int wid = tid >> 5, lane = tid & 31;
    const int wr = wid & 3, wc = wid >> 2;
    const uint32_t sCt = smem_u32(sm.Ct),  sBt = smem_u32(sm.Bt);
    const uint32_t sXt = smem_u32(sm.Xt),  sSp = smem_u32(sm.Spt);
    const uint32_t sW2 = smem_u32(sm.W2);
    const int l0 = wr * 16 + (lane >> 2);

    {
        float accw[4][4];
#pragma unroll
        for (int i = 0; i < 4; i++)
#pragma unroll
            for (int j = 0; j < 4; j++) accw[i][j] = 0.f;
#pragma unroll
        for (int ks = 0; ks < 4; ks++) {
            uint32_t a[4];
            int ar = wr * 16 + (lane & 15);
            int ga = 2 * ks + (lane >> 4);
            ldsm4(a, sCt + ar * 128 + ((ga ^ (ar & 7)) << 4));
#pragma unroll
            for (int nt = 0; nt < 4; nt++) {
                uint32_t bb2[2];
                int sr = wc * 32 + nt * 8 + (lane & 7);
                int gb = 2 * ks + ((lane >> 3) & 1);
                ldsm2(bb2, sBt + sr * 128 + ((gb ^ (sr & 7)) << 4));
                mma16816h(accw[nt], a, bb2[0], bb2[1]);
            }
        }
        float A0 = sm.Acum[l0], A1 = sm.Acum[l0 + 8];
#pragma unroll
        for (int nt = 0; nt < 4; nt++) {
            int s0 = wc * 32 + nt * 8 + (lane & 3) * 2;
            float As0 = sm.Acum[s0], As1 = sm.Acum[s0 + 1];
            float w00 = (s0     <= l0) ? expf(A0 - As0) : 0.f;
            float w01 = (s0 + 1 <= l0) ? expf(A0 - As1) : 0.f;
            float w10 = (s0     <= l0 + 8) ? expf(A1 - As0) : 0.f;
            float w11 = (s0 + 1 <= l0 + 8) ? expf(A1 - As1) : 0.f;
            __half2 h0 = __floats2half2_rn(accw[nt][0] * w00, accw[nt][1] * w01);
            __half2 h1 = __floats2half2_rn(accw[nt][2] * w10, accw[nt][3] * w11);
            *(uint32_t*)&sm.W2[swz_idx(l0,     s0)] = *(uint32_t*)&h0;
            *(uint32_t*)&sm.W2[swz_idx(l0 + 8, s0)] = *(uint32_t*)&h1;
        }
    }
    __syncthreads();

    float accd[4][4], acco[4][4];
#pragma unroll
    for (int i = 0; i < 4; i++)
#pragma unroll
        for (int j = 0; j < 4; j++) { accd[i][j] = 0.f; acco[i][j] = 0.f; }

#pragma unroll
    for (int ks = 0; ks < 4; ks++) {
        uint32_t a[4];
        int ar = wr * 16 + (lane & 15);
        int ga = 2 * ks + (lane >> 4);
        ldsm4(a, sW2 + ar * 128 + ((ga ^ (ar & 7)) << 4));
#pragma unroll
        for (int nt = 0; nt < 4; nt++) {
            uint32_t bb2[2];
            int nr = wc * 32 + nt * 8 + (lane & 7);
            int gb = 2 * ks + ((lane >> 3) & 1);
            ldsm2(bb2, sXt + nr * 128 + ((gb ^ (nr & 7)) << 4));
            mma16816h(accd[nt], a, bb2[0], bb2[1]);
        }
    }
#pragma unroll
    for (int ks = 0; ks < 4; ks++) {
        uint32_t a[4];
        int ar = wr * 16 + (lane & 15);
        int ga = 2 * ks + (lane >> 4);
        ldsm4(a, sCt + ar * 128 + ((ga ^ (ar & 7)) << 4));
#pragma unroll
        for (int nt = 0; nt < 4; nt++) {
            uint32_t bb2[2];
            int nr = wc * 32 + nt * 8 + (lane & 7);
            int gb = 2 * ks + ((lane >> 3) & 1);
            ldsm2(bb2, sSp + nr * 128 + ((gb ^ (nr & 7)) << 4));
            mma16816h(acco[nt], a, bb2[0], bb2[1]);
        }
    }

    const float eA0 = sm.eA[l0], eA1 = sm.eA[l0 + 8];
    const size_t row0 = (size_t)(b * cfg::LSEQ + l0g + l0);
#pragma unroll
    for (int nt = 0; nt < 4; nt++) {
        int p = wc * 32 + nt * 8 + (lane & 3) * 2;
        float x00 = sm.Xraw[l0 * 64 + p],      x01 = sm.Xraw[l0 * 64 + p + 1];
        float x10 = sm.Xraw[(l0 + 8) * 64 + p], x11 = sm.Xraw[(l0 + 8) * 64 + p + 1];
        __half2 v0 = __floats2half2_rn(accd[nt][0] + eA0 * acco[nt][0] + Dh * x00,
                                       accd[nt][1] + eA0 * acco[nt][1] + Dh * x01);
        __half2 v1 = __floats2half2_rn(accd[nt][2] + eA1 * acco[nt][2] + Dh * x10,
                                       accd[nt][3] + eA1 * acco[nt][3] + Dh * x11);
        *(__half2*)(y + row0 * cfg::D_INNER + h * cfg::HEADDIM + p)       = v0;
        *(__half2*)(y + (row0 + 8) * cfg::D_INNER + h * cfg::HEADDIM + p) = v1;
    }
}

// ---------------------------------------------------------------------------
// gate + RMSNorm (fp16 y in) -> fp16 pre-swizzled tiles
// ---------------------------------------------------------------------------
__global__ __launch_bounds__(256) void gate_norm_kernel(
    const __half* __restrict__ y, const float* __restrict__ zx,
    const float* __restrict__ nw, __half* __restrict__ nmh)
{
    __shared__ float gbuf[cfg::D_INNER];
    __shared__ float red[8];
    const int t = blockIdx.x;
    const int tid = threadIdx.x;
    const __half* yr = y + (size_t)t * cfg::D_INNER;
    const float* zr = zx + (size_t)t * cfg::D_IN_PROJ;

    float ss = 0.f;
    for (int i = tid * 2; i < cfg::D_INNER; i += 512) {
        float2 yv = __half22float2(*(const __half2*)(yr + i));
        float z0 = zr[i], z1 = zr[i + 1];
        float g0 = yv.x * (z0 / (1.f + expf(-z0)));
        float g1 = yv.y * (z1 / (1.f + expf(-z1)));
        gbuf[i] = g0; gbuf[i + 1] = g1;
        ss = fmaf(g0, g0, ss);
        ss = fmaf(g1, g1, ss);
    }
#pragma unroll
    for (int o = 16; o; o >>= 1) ss += __shfl_xor_sync(0xffffffffu, ss, o);
    if ((tid & 31) == 0) red[tid >> 5] = ss;
    __syncthreads();
    if (tid < 32) {
        float v = (tid < 8) ? red[tid] : 0.f;
#pragma unroll
        for (int o = 4; o; o >>= 1) v += __shfl_xor_sync(0xffffffffu, v, o);
        if (tid == 0) red[0] = v;
    }
    __syncthreads();
    const float scale = rsqrtf(red[0] * (1.f / cfg::D_INNER) + 1e-5f);
    const int tm = t >> 7, r = t & 127;
    const size_t tmbase = (size_t)tm * (cfg::D_INNER / 64) * 8192;
    const uint32_t rx = (uint32_t)(r & 7);
    for (int i = tid; i < cfg::D_INNER; i += 256) {
        float val = gbuf[i] * scale * nw[i];
        int tk = i >> 6, g = (i >> 3) & 7, e = i & 7;
        size_t off = tmbase + (size_t)tk * 8192 + r * 64 + ((g ^ rx) << 3) + e;
        nmh[off] = __float2half_rn(val);
    }
}

// ---------------------------------------------------------------------------
// Host launch
// ---------------------------------------------------------------------------
extern "C" void kernel_launch(void* const* d_in, const int* in_sizes, int n_in,
                              void* d_out, int out_size)
{
    (void)in_sizes; (void)n_in; (void)out_size;
    const float* u       = (const float*)d_in[0];
    const float* W_in    = (const float*)d_in[1];
    const float* conv_w  = (const float*)d_in[2];
    const float* conv_b  = (const float*)d_in[3];
    const float* dt_bias = (const float*)d_in[4];
    const float* A_log   = (const float*)d_in[5];
    const float* D_param = (const float*)d_in[6];
    const float* norm_w  = (const float*)d_in[7];
    const float* W_out   = (const float*)d_in[8];
    float* out = (float*)d_out;

    void *pzx, *pxbc, *pdt, *py, *pG, *psp, *pac;
    void *puh, *pwih, *pnmh, *pwoh;
    cudaGetSymbolAddress(&pzx,  g_zx);
    cudaGetSymbolAddress(&pxbc, g_xbc);
    cudaGetSymbolAddress(&pdt,  g_dt);
    cudaGetSymbolAddress(&py,   g_y);
    cudaGetSymbolAddress(&pG,   g_G);
    cudaGetSymbolAddress(&psp,  g_sprev);
    cudaGetSymbolAddress(&pac,  g_acum);
    cudaGetSymbolAddress(&puh,  g_uh);
    cudaGetSymbolAddress(&pwih, g_wih);
    cudaGetSymbolAddress(&pnmh, g_nmh);
    cudaGetSymbolAddress(&pwoh, g_woh);
    float*  zx  = (float*)pzx;
    __half* xbc = (__half*)pxbc;
    float*  dtb = (float*)pdt;
    __half* yb  = (__half*)py;
    __half* Gb  = (__half*)pG;
    __half* spb = (__half*)psp;
    float*  acb = (float*)pac;
    __half* uh  = (__half*)puh;
    __half* wih = (__half*)pwih;
    __half* nmh = (__half*)pnmh;
    __half* woh = (__half*)pwoh;

    cudaFuncSetAttribute(gemm_mma_kernel, cudaFuncAttributeMaxDynamicSharedMemorySize,
                         mg::SMEM_BYTES);
    cudaFuncSetAttribute(ssd_pass3, cudaFuncAttributeMaxDynamicSharedMemorySize,
                         (int)sizeof(P3S));

    // fp32 -> fp16 pre-swizzled tile converts
    cvt_swz_kernel<<<(cfg::BL / 128) * (cfg::D_MODEL / 64), 256>>>(
        u, uh, cfg::BL, cfg::D_MODEL);
    cvt_swz_kernel<<<(cfg::N1_PAD / 128) * (cfg::D_MODEL / 64), 256>>>(
        W_in, wih, cfg::D_IN_PROJ, cfg::D_MODEL);
    cvt_swz_kernel<<<(cfg::D_MODEL / 128) * (cfg::D_INNER / 64), 256>>>(
        W_out, woh, cfg::D_MODEL, cfg::D_INNER);

    // GEMM1: zx = u @ W_in^T
    {
        dim3 grid(cfg::N1_PAD / 128, cfg::BL / 128);
        gemm_mma_kernel<<<grid, 256, mg::SMEM_BYTES>>>(uh, wih, zx,
                                                       cfg::BL, cfg::D_IN_PROJ, cfg::D_MODEL);
    }
    // fused conv+silu (fp16 out) and dt softplus
    conv_dt_kernel<<<fc::NCONV + fc::NDT, 256>>>(zx, conv_w, conv_b, dt_bias, xbc, dtb);
    // SSD: 3 passes (fp16 intermediates)
    ssd_pass1<<<cfg::NBH * cfg::NCHUNK, 256>>>(xbc, dtb, A_log, Gb, acb);
    ssd_pass2<<<cfg::NBH * 4, 256>>>(Gb, acb, spb);
    ssd_pass3<<<cfg::NBH * cfg::NCHUNK, 256, sizeof(P3S)>>>(
        xbc, dtb, D_param, spb, acb, yb);
    // gate + rmsnorm -> fp16 (swizzled tiles)
    gate_norm_kernel<<<cfg::BL, 256>>>(yb, zx, norm_w, nmh);
    // GEMM2: out = nm @ W_out^T
    {
        dim3 grid(cfg::D_MODEL / 128, cfg::BL / 128);
        gemm_mma_kernel<<<grid, 256, mg::SMEM_BYTES>>>(nmh, woh, out,
                                                       cfg::BL, cfg::D_MODEL, cfg::D_INNER);
    }
}

// round 15
// speedup vs baseline: 1.1802x; 1.0072x over previous
#include <cuda_runtime.h>
#include <cuda_fp16.h>
#include <math.h>
#include <stdint.h>

// ---------------------------------------------------------------------------
// Problem constants (Mamba2 block, B=2, L=4096)
// ---------------------------------------------------------------------------
namespace cfg {
constexpr int D_MODEL   = 2048;
constexpr int D_INNER   = 4096;
constexpr int D_STATE   = 64;
constexpr int D_CONV    = 4;
constexpr int NHEADS    = 64;
constexpr int HEADDIM   = 64;
constexpr int D_XBC     = D_INNER + 2 * D_STATE;              // 4224
constexpr int D_IN_PROJ = 2 * D_INNER + 2 * D_STATE + NHEADS; // 8384
constexpr int LSEQ      = 4096;
constexpr int BATCH     = 2;
constexpr int BL        = BATCH * LSEQ;                       // 8192
constexpr int CHUNK     = 64;
constexpr int NCHUNK    = LSEQ / CHUNK;                       // 64
constexpr int NBH       = BATCH * NHEADS;                     // 128
constexpr int N1_PAD    = 8448;
}

// ---------------------------------------------------------------------------
// Scratch (allocation-free: __device__ globals; zero-init at load)
// ---------------------------------------------------------------------------
__device__ __half g_zx [(size_t)cfg::BL * cfg::D_IN_PROJ];   // fp16 in-proj out
__device__ __half g_xbc[(size_t)cfg::BL * cfg::D_XBC];
__device__ float  g_dt [(size_t)cfg::BL * cfg::NHEADS];
__device__ __half g_y  [(size_t)cfg::BL * cfg::D_INNER];

// SSD intermediates (fp16 storage; fp32 accumulate in registers)
__device__ __half g_G    [(size_t)cfg::NBH * cfg::NCHUNK * 64 * 64];
__device__ __half g_sprev[(size_t)cfg::NBH * cfg::NCHUNK * 64 * 64];
__device__ float  g_acum [(size_t)cfg::NBH * cfg::NCHUNK * 64];

// fp16 operands, PRE-SWIZZLED 16KB tiles (128 rows x 64 cols)
__device__ __half g_uh [(size_t)cfg::BL * cfg::D_MODEL];
__device__ __half g_wih[(size_t)cfg::N1_PAD * cfg::D_MODEL];
__device__ __half g_nmh[(size_t)cfg::BL * cfg::D_INNER];
__device__ __half g_woh[(size_t)cfg::D_MODEL * cfg::D_INNER];

// ---------------------------------------------------------------------------
// PTX helpers
// ---------------------------------------------------------------------------
__device__ __forceinline__ uint32_t smem_u32(const void* p) {
    uint32_t a;
    asm("{ .reg .u64 t; cvta.to.shared.u64 t, %1; cvt.u32.u64 %0, t; }"
        : "=r"(a) : "l"(p));
    return a;
}
__device__ __forceinline__ void ldsm4(uint32_t r[4], uint32_t addr) {
    asm volatile("ldmatrix.sync.aligned.m8n8.x4.shared.b16 {%0,%1,%2,%3}, [%4];"
                 : "=r"(r[0]), "=r"(r[1]), "=r"(r[2]), "=r"(r[3]) : "r"(addr));
}
__device__ __forceinline__ void ldsm2(uint32_t r[2], uint32_t addr) {
    asm volatile("ldmatrix.sync.aligned.m8n8.x2.shared.b16 {%0,%1}, [%2];"
                 : "=r"(r[0]), "=r"(r[1]) : "r"(addr));
}
__device__ __forceinline__ void mma16816h(float c[4], const uint32_t a[4],
                                          uint32_t b0, uint32_t b1) {
    asm volatile(
        "mma.sync.aligned.m16n8k16.row.col.f32.f16.f16.f32 "
        "{%0,%1,%2,%3}, {%4,%5,%6,%7}, {%8,%9}, {%0,%1,%2,%3};"
        : "+f"(c[0]), "+f"(c[1]), "+f"(c[2]), "+f"(c[3])
        : "r"(a[0]), "r"(a[1]), "r"(a[2]), "r"(a[3]), "r"(b0), "r"(b1));
}
__device__ __forceinline__ void bulk_cp(uint32_t dst, const void* src,
                                        uint32_t bytes, uint32_t mbar) {
    asm volatile(
        "cp.async.bulk.shared::cta.global.mbarrier::complete_tx::bytes "
        "[%0], [%1], %2, [%3];"
        :: "r"(dst), "l"(src), "r"(bytes), "r"(mbar) : "memory");
}
#define MBARRIER_INIT(addr, cnt) \
    asm volatile("mbarrier.init.shared.b64 [%0], %1;" :: "r"(addr), "r"(cnt) : "memory")
#define MBARRIER_EXPECT_TX(addr, bytes) \
    asm volatile("mbarrier.arrive.expect_tx.shared.b64 _, [%0], %1;" \
                 :: "r"(addr), "r"(bytes) : "memory")
#define MBARRIER_ARRIVE(addr) \
    asm volatile("mbarrier.arrive.release.cta.shared::cta.b64 _, [%0];" \
                 :: "r"(addr) : "memory")
#define MBARRIER_WAIT_PARITY(addr, par) do {                                      \
    uint32_t _m = (addr); uint32_t _p = (par); uint32_t _done;                    \
    asm volatile("{\n\t.reg .pred p;\n\t"                                         \
        "mbarrier.try_wait.parity.acquire.cta.shared::cta.b64 p, [%1], %2;\n\t"   \
        "selp.b32 %0, 1, 0, p;\n\t}" : "=r"(_done) : "r"(_m), "r"(_p) : "memory");\
    if (!_done) {                                                                 \
        asm volatile("{\n\t.reg .pred P1;\n\t"                                    \
        "WL_%=:\n\t"                                                              \
        "mbarrier.try_wait.parity.acquire.cta.shared::cta.b64 P1, [%0], %1, 0x989680;\n\t" \
        "@P1 bra.uni WD_%=;\n\tbra.uni WL_%=;\n\tWD_%=:\n\t}"                     \
        :: "r"(_m), "r"(_p) : "memory");                                          \
    } } while (0)

__device__ __forceinline__ int swz_idx(int row, int col) {
    return row * 64 + (((col >> 3) ^ (row & 7)) << 3) + (col & 7);
}

// output store helper (fp32 or fp16)
__device__ __forceinline__ void store2(float* p, float a, float b) {
    *(float2*)p = make_float2(a, b);
}
__device__ __forceinline__ void store2(__half* p, float a, float b) {
    *(__half2*)p = __floats2half2_rn(a, b);
}

// ---------------------------------------------------------------------------
// HMMA fp16 GEMM, 128x128x64, 2 CTA/SM, warp-decoupled mbarrier pipeline
// (R14 WIN config). Output type templated (fp32 final / fp16 intermediate).
// ---------------------------------------------------------------------------
namespace mg {
constexpr int KT    = 64;
constexpr int TILEB = 128 * KT * 2;          // 16384 B
constexpr int STAGE = 2 * TILEB;             // 32768 B
constexpr int STAGES = 3;
constexpr int MBAR_OFF = STAGES * STAGE;     // 98304
constexpr int SMEM_BYTES = MBAR_OFF + 64;
}

template <typename TO>
__global__ __launch_bounds__(256, 2) void gemm_mma_kernel(
    const __half* __restrict__ At, const __half* __restrict__ Bt,
    TO* __restrict__ C, int M, int N, int K)
{
    extern __shared__ char smraw[];
    const uint32_t sb = smem_u32(smraw);
    const int tid  = threadIdx.x;
    const int bm   = blockIdx.y * 128;
    const int bn   = blockIdx.x * 128;
    const int wid  = tid >> 5, lane = tid & 31;
    const int wm   = wid & 1;
    const int wn   = wid >> 1;
    const int NK   = K >> 6;

    const __half* Abase = At + (size_t)blockIdx.y * NK * 8192;
    const __half* Bbase = Bt + (size_t)blockIdx.x * NK * 8192;
    const uint32_t mb = sb + mg::MBAR_OFF;

    if (tid == 0) {
        MBARRIER_INIT(mb,      1u);    // full0
        MBARRIER_INIT(mb + 8,  1u);    // full1
        MBARRIER_INIT(mb + 16, 1u);    // full2
        MBARRIER_INIT(mb + 24, 256u);  // empty0
        MBARRIER_INIT(mb + 32, 256u);  // empty1
        MBARRIER_INIT(mb + 40, 256u);  // empty2
    }
    __syncthreads();

    auto issue = [&](int stage, int kblk) {
        const uint32_t m = mb + stage * 8;
        MBARRIER_EXPECT_TX(m, (uint32_t)mg::STAGE);
        const uint32_t d = sb + stage * mg::STAGE;
        bulk_cp(d,             Abase + (size_t)kblk * 8192, mg::TILEB, m);
        bulk_cp(d + mg::TILEB, Bbase + (size_t)kblk * 8192, mg::TILEB, m);
    };

    float acc[4][4][4];
#pragma unroll
    for (int i = 0; i < 4; i++)
#pragma unroll
        for (int j = 0; j < 4; j++)
#pragma unroll
            for (int q = 0; q < 4; q++) acc[i][j][q] = 0.f;

    if (tid == 0) { issue(0, 0); issue(1, 1); }

    for (int kb = 0; kb < NK; kb++) {
        const int st = kb % mg::STAGES;

        if (kb + 2 < NK && tid == 0) {
            const int kblk = kb + 2, s2 = kblk % mg::STAGES;
            if (kblk >= 3)
                MBARRIER_WAIT_PARITY(mb + 24 + s2 * 8,
                                     (uint32_t)(((kblk / 3) - 1) & 1));
            issue(s2, kblk);
        }

        MBARRIER_WAIT_PARITY(mb + st * 8, (uint32_t)((kb / 3) & 1));

        const uint32_t sA = sb + st * mg::STAGE;
        const uint32_t sB = sA + mg::TILEB;

#pragma unroll
        for (int ks = 0; ks < 4; ks++) {
            uint32_t bf[4][2];
#pragma unroll
            for (int nt = 0; nt < 4; nt++) {
                int nr = wn * 32 + nt * 8 + (lane & 7);
                int g  = 2 * ks + ((lane >> 3) & 1);
                uint32_t off = nr * 128 + (((g ^ (nr & 7))) << 4);
                ldsm2(bf[nt], sB + off);
            }
            uint32_t a[4][4];
#pragma unroll
            for (int mt = 0; mt < 4; mt++) {
                int ar = wm * 64 + mt * 16 + (lane & 15);
                int g  = 2 * ks + (lane >> 4);
                uint32_t off = ar * 128 + (((g ^ (ar & 7))) << 4);
                ldsm4(a[mt], sA + off);
            }
#pragma unroll
            for (int mt = 0; mt < 4; mt++)
#pragma unroll
                for (int nt = 0; nt < 4; nt++)
                    mma16816h(acc[mt][nt], a[mt], bf[nt][0], bf[nt][1]);
        }
        MBARRIER_ARRIVE(mb + 24 + st * 8);
    }

#pragma unroll
    for (int mt = 0; mt < 4; mt++) {
#pragma unroll
        for (int nt = 0; nt < 4; nt++) {
            int row = bm + wm * 64 + mt * 16 + (lane >> 2);
            int col = bn + wn * 32 + nt * 8 + (lane & 3) * 2;
            if (col < N) {
                store2(C + (size_t)row * N + col, acc[mt][nt][0], acc[mt][nt][1]);
                store2(C + (size_t)(row + 8) * N + col, acc[mt][nt][2], acc[mt][nt][3]);
            }
        }
    }
}

// ---------------------------------------------------------------------------
// fp32 row-major -> fp16 pre-swizzled 16KB tiles
// ---------------------------------------------------------------------------
__global__ __launch_bounds__(256) void cvt_swz_kernel(
    const float* __restrict__ src, __half* __restrict__ dst, int Mreal, int K)
{
    const int NKt = K >> 6;
    const int tile = blockIdx.x;
    const int tm = tile / NKt, tk = tile % NKt;
    __half* d = dst + (size_t)tile * 8192;
#pragma unroll
    for (int it = 0; it < 4; it++) {
        int id = it * 256 + threadIdx.x;
        int r  = id >> 3, g = id & 7;
        int grow = tm * 128 + r;
        uint32_t off = (uint32_t)(r * 64 + ((g ^ (r & 7)) << 3));
        uint4 pk;
        if (grow < Mreal) {
            const float* s = src + (size_t)grow * K + tk * 64 + g * 8;
            float4 v0 = *(const float4*)s;
            float4 v1 = *(const float4*)(s + 4);
            __half2 h0 = __floats2half2_rn(v0.x, v0.y);
            __half2 h1 = __floats2half2_rn(v0.z, v0.w);
            __half2 h2 = __floats2half2_rn(v1.x, v1.y);
            __half2 h3 = __floats2half2_rn(v1.z, v1.w);
            pk.x = *(uint32_t*)&h0; pk.y = *(uint32_t*)&h1;
            pk.z = *(uint32_t*)&h2; pk.w = *(uint32_t*)&h3;
        } else {
            pk = make_uint4(0, 0, 0, 0);
        }
        *(uint4*)(d + off) = pk;
    }
}

// ---------------------------------------------------------------------------
// Fused conv+silu (fp16 in/out) and dt softplus (fp16 in)
// ---------------------------------------------------------------------------
namespace fc {
constexpr int NCONV = (cfg::BL * cfg::D_XBC + 255) / 256;
constexpr int NDT   = (cfg::BL * cfg::NHEADS + 255) / 256;
}

__global__ void conv_dt_kernel(const __half* __restrict__ zx,
                               const float* __restrict__ cw,
                               const float* __restrict__ cb,
                               const float* __restrict__ dt_bias,
                               __half* __restrict__ xbc_out,
                               float* __restrict__ dt_out)
{
    int blk = blockIdx.x;
    if (blk < fc::NCONV) {
        int idx = blk * 256 + threadIdx.x;
        if (idx >= cfg::BL * cfg::D_XBC) return;
        int j = idx % cfg::D_XBC;
        int t = idx / cfg::D_XBC;
        int l = t & (cfg::LSEQ - 1);
        int b = t >> 12;
        float v = cb[j];
#pragma unroll
        for (int k = 0; k < cfg::D_CONV; k++) {
            int ls = l + k - (cfg::D_CONV - 1);
            if (ls >= 0)
                v = fmaf(cw[j * cfg::D_CONV + k],
                         __half2float(zx[(size_t)(b * cfg::LSEQ + ls) * cfg::D_IN_PROJ
                                         + cfg::D_INNER + j]), v);
        }
        xbc_out[(size_t)t * cfg::D_XBC + j] = __float2half_rn(v / (1.f + expf(-v)));
    } else {
        int idx = (blk - fc::NCONV) * 256 + threadIdx.x;
        if (idx >= cfg::BL * cfg::NHEADS) return;
        int h = idx & 63;
        int t = idx >> 6;
        float x = __half2float(zx[(size_t)t * cfg::D_IN_PROJ + cfg::D_INNER + cfg::D_XBC + h])
                  + dt_bias[h];
        dt_out[idx] = (x > 20.f) ? x : log1pf(expf(x));
    }
}

// ---------------------------------------------------------------------------
// SSD pass 1 (HMMA, fp16 in/out)
// ---------------------------------------------------------------------------
__global__ __launch_bounds__(256) void ssd_pass1(
    const __half* __restrict__ xbc, const float* __restrict__ dtg,
    const float* __restrict__ A_log,
    __half* __restrict__ G, float* __restrict__ acum)
{
    __shared__ __half Bw[4096];
    __shared__ __half Xt[4096];
    __shared__ float Acum[64], ws[64], dts[64];
    const int blk = blockIdx.x;
    const int c = blk & 63, bh = blk >> 6;
    const int h = bh & 63, b = bh >> 6;
    const int tid = threadIdx.x;
    const float Aneg = -expf(A_log[h]);
    const int l0g = c * cfg::CHUNK;

    if (tid < 64) {
        const int lane = tid & 31;
        size_t row = (size_t)(b * cfg::LSEQ + l0g + tid);
        float dtv = dtg[row * cfg::NHEADS + h];
        dts[tid] = dtv;
        float v = Aneg * dtv;
#pragma unroll
        for (int o = 1; o < 32; o <<= 1) {
            float n = __shfl_up_sync(0xffffffffu, v, o);
            if (lane >= o) v += n;
        }
        Acum[tid] = v;
    }
    __syncthreads();
    if (tid < 64) {
        float v = Acum[tid] + ((tid >= 32) ? Acum[31] : 0.f);
        Acum[tid] = v;
    }
    __syncthreads();
    if (tid < 64) {
        ws[tid] = expf(Acum[63] - Acum[tid]);
        acum[(size_t)blk * 64 + tid] = Acum[tid];
    }
    __syncthreads();

    for (int idx = tid; idx < 1024; idx += 256) {
        int l = idx >> 4, q4 = (idx & 15) * 4;
        size_t row = (size_t)(b * cfg::LSEQ + l0g + l);
        const __half* xr = xbc + row * cfg::D_XBC;
        float dtv = dts[l], wv = ws[l];
        uint2 xb = *(const uint2*)(xr + h * cfg::HEADDIM + q4);
        uint2 bb = *(const uint2*)(xr + cfg::D_INNER + q4);
        float2 x01 = __half22float2(*(__half2*)&xb.x);
        float2 x23 = __half22float2(*(__half2*)&xb.y);
        float2 b01 = __half22float2(*(__half2*)&bb.x);
        float2 b23 = __half22float2(*(__half2*)&bb.y);
        float xa[4] = {x01.x, x01.y, x23.x, x23.y};
        float ba[4] = {b01.x, b01.y, b23.x, b23.y};
#pragma unroll
        for (int e = 0; e < 4; e++) {
            int p = q4 + e;
            Xt[swz_idx(p, l)] = __float2half_rn(xa[e] * dtv);
            Bw[swz_idx(p, l)] = __float2half_rn(ba[e] * wv);
        }
    }
    __syncthreads();

    const int wid = tid >> 5, lane = tid & 31;
    const int wr = wid & 3, wc = wid >> 2;
    const uint32_t sBw = smem_u32(Bw), sXt = smem_u32(Xt);
    float acc[4][4];
#pragma unroll
    for (int i = 0; i < 4; i++)
#pragma unroll
        for (int j = 0; j < 4; j++) acc[i][j] = 0.f;

#pragma unroll
    for (int ks = 0; ks < 4; ks++) {
        uint32_t a[4];
        {
            int ar = wr * 16 + (lane & 15);
            int g  = 2 * ks + (lane >> 4);
            ldsm4(a, sBw + ar * 128 + ((g ^ (ar & 7)) << 4));
        }
#pragma unroll
        for (int nt = 0; nt < 4; nt++) {
            uint32_t bb2[2];
            int nr = wc * 32 + nt * 8 + (lane & 7);
            int g  = 2 * ks + ((lane >> 3) & 1);
            ldsm2(bb2, sXt + nr * 128 + ((g ^ (nr & 7)) << 4));
            mma16816h(acc[nt], a, bb2[0], bb2[1]);
        }
    }

    __half* gout = G + (size_t)blk * 4096;
    const int n0 = wr * 16 + (lane >> 2);
#pragma unroll
    for (int nt = 0; nt < 4; nt++) {
        int p = wc * 32 + nt * 8 + (lane & 3) * 2;
        __half2 v0 = __floats2half2_rn(acc[nt][0], acc[nt][1]);
        __half2 v1 = __floats2half2_rn(acc[nt][2], acc[nt][3]);
        *(__half2*)(gout + n0 * 64 + p)       = v0;
        *(__half2*)(gout + (n0 + 8) * 64 + p) = v1;
    }
}

// ---------------------------------------------------------------------------
// SSD pass 2 (fp16 storage, fp32 accumulate)
// ---------------------------------------------------------------------------
__global__ __launch_bounds__(256) void ssd_pass2(
    const __half* __restrict__ G, const float* __restrict__ acum,
    __half* __restrict__ sprev)
{
    __shared__ float eAc[cfg::NCHUNK];
    const int bh    = blockIdx.x >> 2;
    const int slice = blockIdx.x & 3;
    const int tid   = threadIdx.x;
    if (tid < cfg::NCHUNK)
        eAc[tid] = expf(acum[((size_t)bh * cfg::NCHUNK + tid) * 64 + 63]);
    __syncthreads();

    const int f4 = slice * 256 + tid;
    float4 S = make_float4(0.f, 0.f, 0.f, 0.f);
    const size_t bhbase = (size_t)bh * cfg::NCHUNK * 4096;
    for (int c = 0; c < cfg::NCHUNK; c++) {
        const size_t base = bhbase + (size_t)c * 4096 + f4 * 4;
        uint2 sp;
        __half2 s01 = __floats2half2_rn(S.x, S.y);
        __half2 s23 = __floats2half2_rn(S.z, S.w);
        sp.x = *(uint32_t*)&s01; sp.y = *(uint32_t*)&s23;
        *(uint2*)(sprev + base) = sp;
        uint2 gp = *(const uint2*)(G + base);
        float2 g01 = __half22float2(*(__half2*)&gp.x);
        float2 g23 = __half22float2(*(__half2*)&gp.y);
        float ea = eAc[c];
        S.x = fmaf(ea, S.x, g01.x);
        S.y = fmaf(ea, S.y, g01.y);
        S.z = fmaf(ea, S.z, g23.x);
        S.w = fmaf(ea, S.w, g23.y);
    }
}

// ---------------------------------------------------------------------------
// SSD pass 3 (HMMA, fp16 in; fp16 y out)
// ---------------------------------------------------------------------------
struct P3S {
    __half Ct [4096];
    __half Bt [4096];
    __half Xt [4096];
    __half Spt[4096];
    __half W2 [4096];
    float  Xraw[4096];
    float  Acum[64], eA[64], dts[64];
};

__global__ __launch_bounds__(256) void ssd_pass3(
    const __half* __restrict__ xbc, const float* __restrict__ dtg,
    const float* __restrict__ D_param,
    const __half* __restrict__ sprev, const float* __restrict__ acum,
    __half* __restrict__ y)
{
    extern __shared__ char smraw[];
    P3S& sm = *reinterpret_cast<P3S*>(smraw);
    const int blk = blockIdx.x;
    const int c = blk & 63, bh = blk >> 6;
    const int h = bh & 63, b = bh >> 6;
    const int tid = threadIdx.x;
    const float Dh = D_param[h];
    const int l0g = c * cfg::CHUNK;

    if (tid < 64) {
        size_t row = (size_t)(b * cfg::LSEQ + l0g + tid);
        sm.dts[tid] = dtg[row * cfg::NHEADS + h];
        float a = acum[(size_t)blk * 64 + tid];
        sm.Acum[tid] = a;
        sm.eA[tid]   = expf(a);
    }
    __syncthreads();

    const __half* spin = sprev + (size_t)blk * 4096;
    for (int idx = tid; idx < 1024; idx += 256) {
        int r = idx >> 4, q4 = (idx & 15) * 4;
        size_t grow = (size_t)(b * cfg::LSEQ + l0g + r);
        const __half* xr = xbc + grow * cfg::D_XBC;
        float dtv = sm.dts[r];
        uint2 xb = *(const uint2*)(xr + h * cfg::HEADDIM + q4);
        uint2 bb = *(const uint2*)(xr + cfg::D_INNER + q4);
        uint2 cb2 = *(const uint2*)(xr + cfg::D_INNER + cfg::D_STATE + q4);
        uint2 sp = *(const uint2*)(spin + r * 64 + q4);

        int ci = swz_idx(r, q4);
        *(uint2*)&sm.Ct[ci] = cb2;
        *(uint2*)&sm.Bt[ci] = bb;

        float2 x01 = __half22float2(*(__half2*)&xb.x);
        float2 x23 = __half22float2(*(__half2*)&xb.y);
        float xa[4] = {x01.x, x01.y, x23.x, x23.y};
        *(float4*)&sm.Xraw[r * 64 + q4] = make_float4(xa[0], xa[1], xa[2], xa[3]);

        const __half* spv = (const __half*)&sp;
#pragma unroll
        for (int e = 0; e < 4; e++) {
            int p = q4 + e;
            sm.Xt [swz_idx(p, r)] = __float2half_rn(xa[e] * dtv);
            sm.Spt[swz_idx(p, r)] = spv[e];
        }
    }
    __syncthreads();

    const int wid = tid >> 5, lane = tid & 31;
    const int wr = wid & 3, wc = wid >> 2;
    const uint32_t sCt = smem_u32(sm.Ct),  sBt = smem_u32(sm.Bt);
    const uint32_t sXt = smem_u32(sm.Xt),  sSp = smem_u32(sm.Spt);
    const uint32_t sW2 = smem_u32(sm.W2);
    const int l0 = wr * 16 + (lane >> 2);

    {
        float accw[4][4];
#pragma unroll
        for (int i = 0; i < 4; i++)
#pragma unroll
            for (int j = 0; j < 4; j++) accw[i][j] = 0.f;
#pragma unroll
        for (int ks = 0; ks < 4; ks++) {
            uint32_t a[4];
            int ar = wr * 16 + (lane & 15);
            int ga = 2 * ks + (lane >> 4);
            ldsm4(a, sCt + ar * 128 + ((ga ^ (ar & 7)) << 4));
#pragma unroll
            for (int nt = 0; nt < 4; nt++) {
                uint32_t bb2[2];
                int sr = wc * 32 + nt * 8 + (lane & 7);
                int gb = 2 * ks + ((lane >> 3) & 1);
                ldsm2(bb2, sBt + sr * 128 + ((gb ^ (sr & 7)) << 4));
                mma16816h(accw[nt], a, bb2[0], bb2[1]);
            }
        }
        float A0 = sm.Acum[l0], A1 = sm.Acum[l0 + 8];
#pragma unroll
        for (int nt = 0; nt < 4; nt++) {
            int s0 = wc * 32 + nt * 8 + (lane & 3) * 2;
            float As0 = sm.Acum[s0], As1 = sm.Acum[s0 + 1];
            float w00 = (s0     <= l0) ? expf(A0 - As0) : 0.f;
            float w01 = (s0 + 1 <= l0) ? expf(A0 - As1) : 0.f;
            float w10 = (s0     <= l0 + 8) ? expf(A1 - As0) : 0.f;
            float w11 = (s0 + 1 <= l0 + 8) ? expf(A1 - As1) : 0.f;
            __half2 h0 = __floats2half2_rn(accw[nt][0] * w00, accw[nt][1] * w01);
            __half2 h1 = __floats2half2_rn(accw[nt][2] * w10, accw[nt][3] * w11);
            *(uint32_t*)&sm.W2[swz_idx(l0,     s0)] = *(uint32_t*)&h0;
            *(uint32_t*)&sm.W2[swz_idx(l0 + 8, s0)] = *(uint32_t*)&h1;
        }
    }
    __syncthreads();

    float accd[4][4], acco[4][4];
#pragma unroll
    for (int i = 0; i < 4; i++)
#pragma unroll
        for (int j = 0; j < 4; j++) { accd[i][j] = 0.f; acco[i][j] = 0.f; }

#pragma unroll
    for (int ks = 0; ks < 4; ks++) {
        uint32_t a[4];
        int ar = wr * 16 + (lane & 15);
        int ga = 2 * ks + (lane >> 4);
        ldsm4(a, sW2 + ar * 128 + ((ga ^ (ar & 7)) << 4));
#pragma unroll
        for (int nt = 0; nt < 4; nt++) {
            uint32_t bb2[2];
            int nr = wc * 32 + nt * 8 + (lane & 7);
            int gb = 2 * ks + ((lane >> 3) & 1);
            ldsm2(bb2, sXt + nr * 128 + ((gb ^ (nr & 7)) << 4));
            mma16816h(accd[nt], a, bb2[0], bb2[1]);
        }
    }
#pragma unroll
    for (int ks = 0; ks < 4; ks++) {
        uint32_t a[4];
        int ar = wr * 16 + (lane & 15);
        int ga = 2 * ks + (lane >> 4);
        ldsm4(a, sCt + ar * 128 + ((ga ^ (ar & 7)) << 4));
#pragma unroll
        for (int nt = 0; nt < 4; nt++) {
            uint32_t bb2[2];
            int nr = wc * 32 + nt * 8 + (lane & 7);
            int gb = 2 * ks + ((lane >> 3) & 1);
            ldsm2(bb2, sSp + nr * 128 + ((gb ^ (nr & 7)) << 4));
            mma16816h(acco[nt], a, bb2[0], bb2[1]);
        }
    }

    const float eA0 = sm.eA[l0], eA1 = sm.eA[l0 + 8];
    const size_t row0 = (size_t)(b * cfg::LSEQ + l0g + l0);
#pragma unroll
    for (int nt = 0; nt < 4; nt++) {
        int p = wc * 32 + nt * 8 + (lane & 3) * 2;
        float x00 = sm.Xraw[l0 * 64 + p],      x01 = sm.Xraw[l0 * 64 + p + 1];
        float x10 = sm.Xraw[(l0 + 8) * 64 + p], x11 = sm.Xraw[(l0 + 8) * 64 + p + 1];
        __half2 v0 = __floats2half2_rn(accd[nt][0] + eA0 * acco[nt][0] + Dh * x00,
                                       accd[nt][1] + eA0 * acco[nt][1] + Dh * x01);
        __half2 v1 = __floats2half2_rn(accd[nt][2] + eA1 * acco[nt][2] + Dh * x10,
                                       accd[nt][3] + eA1 * acco[nt][3] + Dh * x11);
        *(__half2*)(y + row0 * cfg::D_INNER + h * cfg::HEADDIM + p)       = v0;
        *(__half2*)(y + (row0 + 8) * cfg::D_INNER + h * cfg::HEADDIM + p) = v1;
    }
}

// ---------------------------------------------------------------------------
// gate + RMSNorm (fp16 y & z in) -> fp16 pre-swizzled tiles
// ---------------------------------------------------------------------------
__global__ __launch_bounds__(256) void gate_norm_kernel(
    const __half* __restrict__ y, const __half* __restrict__ zx,
    const float* __restrict__ nw, __half* __restrict__ nmh)
{
    __shared__ float gbuf[cfg::D_INNER];
    __shared__ float red[8];
    const int t = blockIdx.x;
    const int tid = threadIdx.x;
    const __half* yr = y + (size_t)t * cfg::D_INNER;
    const __half* zr = zx + (size_t)t * cfg::D_IN_PROJ;

    float ss = 0.f;
    for (int i = tid * 2; i < cfg::D_INNER; i += 512) {
        float2 yv = __half22float2(*(const __half2*)(yr + i));
        float2 zv = __half22float2(*(const __half2*)(zr + i));
        float g0 = yv.x * (zv.x / (1.f + expf(-zv.x)));
        float g1 = yv.y * (zv.y / (1.f + expf(-zv.y)));
        gbuf[i] = g0; gbuf[i + 1] = g1;
        ss = fmaf(g0, g0, ss);
        ss = fmaf(g1, g1, ss);
    }
#pragma unroll
    for (int o = 16; o; o >>= 1) ss += __shfl_xor_sync(0xffffffffu, ss, o);
    if ((tid & 31) == 0) red[tid >> 5] = ss;
    __syncthreads();
    if (tid < 32) {
        float v = (tid < 8) ? red[tid] : 0.f;
#pragma unroll
        for (int o = 4; o; o >>= 1) v += __shfl_xor_sync(0xffffffffu, v, o);
        if (tid == 0) red[0] = v;
    }
    __syncthreads();
    const float scale = rsqrtf(red[0] * (1.f / cfg::D_INNER) + 1e-5f);
    const int tm = t >> 7, r = t & 127;
    const size_t tmbase = (size_t)tm * (cfg::D_INNER / 64) * 8192;
    const uint32_t rx = (uint32_t)(r & 7);
    for (int i = tid; i < cfg::D_INNER; i += 256) {
        float val = gbuf[i] * scale * nw[i];
        int tk = i >> 6, g = (i >> 3) & 7, e = i & 7;
        size_t off = tmbase + (size_t)tk * 8192 + r * 64 + ((g ^ rx) << 3) + e;
        nmh[off] = __float2half_rn(val);
    }
}

// ---------------------------------------------------------------------------
// Host launch
// ---------------------------------------------------------------------------
extern "C" void kernel_launch(void* const* d_in, const int* in_sizes, int n_in,
                              void* d_out, int out_size)
{
    (void)in_sizes; (void)n_in; (void)out_size;
    const float* u       = (const float*)d_in[0];
    const float* W_in    = (const float*)d_in[1];
    const float* conv_w  = (const float*)d_in[2];
    const float* conv_b  = (const float*)d_in[3];
    const float* dt_bias = (const float*)d_in[4];
    const float* A_log   = (const float*)d_in[5];
    const float* D_param = (const float*)d_in[6];
    const float* norm_w  = (const float*)d_in[7];
    const float* W_out   = (const float*)d_in[8];
    float* out = (float*)d_out;

    void *pzx, *pxbc, *pdt, *py, *pG, *psp, *pac;
    void *puh, *pwih, *pnmh, *pwoh;
    cudaGetSymbolAddress(&pzx,  g_zx);
    cudaGetSymbolAddress(&pxbc, g_xbc);
    cudaGetSymbolAddress(&pdt,  g_dt);
    cudaGetSymbolAddress(&py,   g_y);
    cudaGetSymbolAddress(&pG,   g_G);
    cudaGetSymbolAddress(&psp,  g_sprev);
    cudaGetSymbolAddress(&pac,  g_acum);
    cudaGetSymbolAddress(&puh,  g_uh);
    cudaGetSymbolAddress(&pwih, g_wih);
    cudaGetSymbolAddress(&pnmh, g_nmh);
    cudaGetSymbolAddress(&pwoh, g_woh);
    __half* zx  = (__half*)pzx;
    __half* xbc = (__half*)pxbc;
    float*  dtb = (float*)pdt;
    __half* yb  = (__half*)py;
    __half* Gb  = (__half*)pG;
    __half* spb = (__half*)psp;
    float*  acb = (float*)pac;
    __half* uh  = (__half*)puh;
    __half* wih = (__half*)pwih;
    __half* nmh = (__half*)pnmh;
    __half* woh = (__half*)pwoh;

    cudaFuncSetAttribute(gemm_mma_kernel<__half>,
                         cudaFuncAttributeMaxDynamicSharedMemorySize, mg::SMEM_BYTES);
    cudaFuncSetAttribute(gemm_mma_kernel<float>,
                         cudaFuncAttributeMaxDynamicSharedMemorySize, mg::SMEM_BYTES);
    cudaFuncSetAttribute(ssd_pass3, cudaFuncAttributeMaxDynamicSharedMemorySize,
                         (int)sizeof(P3S));

    // fp32 -> fp16 pre-swizzled tile converts
    cvt_swz_kernel<<<(cfg::BL / 128) * (cfg::D_MODEL / 64), 256>>>(
        u, uh, cfg::BL, cfg::D_MODEL);
    cvt_swz_kernel<<<(cfg::N1_PAD / 128) * (cfg::D_MODEL / 64), 256>>>(
        W_in, wih, cfg::D_IN_PROJ, cfg::D_MODEL);
    cvt_swz_kernel<<<(cfg::D_MODEL / 128) * (cfg::D_INNER / 64), 256>>>(
        W_out, woh, cfg::D_MODEL, cfg::D_INNER);

    // GEMM1: zx(fp16) = u @ W_in^T
    {
        dim3 grid(cfg::N1_PAD / 128, cfg::BL / 128);
        gemm_mma_kernel<__half><<<grid, 256, mg::SMEM_BYTES>>>(
            uh, wih, zx, cfg::BL, cfg::D_IN_PROJ, cfg::D_MODEL);
    }
    // fused conv+silu (fp16 in/out) and dt softplus
    conv_dt_kernel<<<fc::NCONV + fc::NDT, 256>>>(zx, conv_w, conv_b, dt_bias, xbc, dtb);
    // SSD: 3 passes (fp16 intermediates)
    ssd_pass1<<<cfg::NBH * cfg::NCHUNK, 256>>>(xbc, dtb, A_log, Gb, acb);
    ssd_pass2<<<cfg::NBH * 4, 256>>>(Gb, acb, spb);
    ssd_pass3<<<cfg::NBH * cfg::NCHUNK, 256, sizeof(P3S)>>>(
        xbc, dtb, D_param, spb, acb, yb);
    // gate + rmsnorm -> fp16 (swizzled tiles)
    gate_norm_kernel<<<cfg::BL, 256>>>(yb, zx, norm_w, nmh);
    // GEMM2: out(fp32) = nm @ W_out^T
    {
        dim3 grid(cfg::D_MODEL / 128, cfg::BL / 128);
        gemm_mma_kernel<float><<<grid, 256, mg::SMEM_BYTES>>>(
            nmh, woh, out, cfg::BL, cfg::D_MODEL, cfg::D_INNER);
    }
}

// round 16
// speedup vs baseline: 1.2349x; 1.0463x over previous
#include <cuda_runtime.h>
#include <cuda_fp16.h>
#include <math.h>
#include <stdint.h>

// ---------------------------------------------------------------------------
// Problem constants (Mamba2 block, B=2, L=4096)
// ---------------------------------------------------------------------------
namespace cfg {
constexpr int D_MODEL   = 2048;
constexpr int D_INNER   = 4096;
constexpr int D_STATE   = 64;
constexpr int D_CONV    = 4;
constexpr int NHEADS    = 64;
constexpr int HEADDIM   = 64;
constexpr int D_XBC     = D_INNER + 2 * D_STATE;              // 4224
constexpr int D_IN_PROJ = 2 * D_INNER + 2 * D_STATE + NHEADS; // 8384
constexpr int LSEQ      = 4096;
constexpr int BATCH     = 2;
constexpr int BL        = BATCH * LSEQ;                       // 8192
constexpr int CHUNK     = 64;
constexpr int NCHUNK    = LSEQ / CHUNK;                       // 64
constexpr int NBH       = BATCH * NHEADS;                     // 128
constexpr int N1_PAD    = 8448;
}

// ---------------------------------------------------------------------------
// Scratch (allocation-free: __device__ globals; zero-init at load)
// ---------------------------------------------------------------------------
__device__ __half g_zx [(size_t)cfg::BL * cfg::D_IN_PROJ];
__device__ __half g_xbc[(size_t)cfg::BL * cfg::D_XBC];
__device__ float  g_dt [(size_t)cfg::BL * cfg::NHEADS];
__device__ __half g_y  [(size_t)cfg::BL * cfg::D_INNER];

// SSD intermediates
__device__ __half g_G    [(size_t)cfg::NBH * cfg::NCHUNK * 64 * 64];
__device__ __half g_sprev[(size_t)cfg::NBH * cfg::NCHUNK * 64 * 64];
__device__ float  g_acum [(size_t)cfg::NBH * cfg::NCHUNK * 64];

// fp16 operands, PRE-SWIZZLED 16KB tiles (128 rows x 64 cols)
__device__ __half g_uh [(size_t)cfg::BL * cfg::D_MODEL];
__device__ __half g_wih[(size_t)cfg::N1_PAD * cfg::D_MODEL];
__device__ __half g_nmh[(size_t)cfg::BL * cfg::D_INNER];
__device__ __half g_woh[(size_t)cfg::D_MODEL * cfg::D_INNER];

// ---------------------------------------------------------------------------
// PTX helpers
// ---------------------------------------------------------------------------
__device__ __forceinline__ uint32_t smem_u32(const void* p) {
    uint32_t a;
    asm("{ .reg .u64 t; cvta.to.shared.u64 t, %1; cvt.u32.u64 %0, t; }"
        : "=r"(a) : "l"(p));
    return a;
}
__device__ __forceinline__ void ldsm4(uint32_t r[4], uint32_t addr) {
    asm volatile("ldmatrix.sync.aligned.m8n8.x4.shared.b16 {%0,%1,%2,%3}, [%4];"
                 : "=r"(r[0]), "=r"(r[1]), "=r"(r[2]), "=r"(r[3]) : "r"(addr));
}
__device__ __forceinline__ void ldsm2(uint32_t r[2], uint32_t addr) {
    asm volatile("ldmatrix.sync.aligned.m8n8.x2.shared.b16 {%0,%1}, [%2];"
                 : "=r"(r[0]), "=r"(r[1]) : "r"(addr));
}
__device__ __forceinline__ void ldsm4t(uint32_t r[4], uint32_t addr) {
    asm volatile("ldmatrix.sync.aligned.m8n8.x4.trans.shared.b16 {%0,%1,%2,%3}, [%4];"
                 : "=r"(r[0]), "=r"(r[1]), "=r"(r[2]), "=r"(r[3]) : "r"(addr));
}
__device__ __forceinline__ void ldsm2t(uint32_t r[2], uint32_t addr) {
    asm volatile("ldmatrix.sync.aligned.m8n8.x2.trans.shared.b16 {%0,%1}, [%2];"
                 : "=r"(r[0]), "=r"(r[1]) : "r"(addr));
}
__device__ __forceinline__ void mma16816h(float c[4], const uint32_t a[4],
                                          uint32_t b0, uint32_t b1) {
    asm volatile(
        "mma.sync.aligned.m16n8k16.row.col.f32.f16.f16.f32 "
        "{%0,%1,%2,%3}, {%4,%5,%6,%7}, {%8,%9}, {%0,%1,%2,%3};"
        : "+f"(c[0]), "+f"(c[1]), "+f"(c[2]), "+f"(c[3])
        : "r"(a[0]), "r"(a[1]), "r"(a[2]), "r"(a[3]), "r"(b0), "r"(b1));
}
__device__ __forceinline__ void bulk_cp(uint32_t dst, const void* src,
                                        uint32_t bytes, uint32_t mbar) {
    asm volatile(
        "cp.async.bulk.shared::cta.global.mbarrier::complete_tx::bytes "
        "[%0], [%1], %2, [%3];"
        :: "r"(dst), "l"(src), "r"(bytes), "r"(mbar) : "memory");
}
#define MBARRIER_INIT(addr, cnt) \
    asm volatile("mbarrier.init.shared.b64 [%0], %1;" :: "r"(addr), "r"(cnt) : "memory")
#define MBARRIER_EXPECT_TX(addr, bytes) \
    asm volatile("mbarrier.arrive.expect_tx.shared.b64 _, [%0], %1;" \
                 :: "r"(addr), "r"(bytes) : "memory")
#define MBARRIER_ARRIVE(addr) \
    asm volatile("mbarrier.arrive.release.cta.shared::cta.b64 _, [%0];" \
                 :: "r"(addr) : "memory")
#define MBARRIER_WAIT_PARITY(addr, par) do {                                      \
    uint32_t _m = (addr); uint32_t _p = (par); uint32_t _done;                    \
    asm volatile("{\n\t.reg .pred p;\n\t"                                         \
        "mbarrier.try_wait.parity.acquire.cta.shared::cta.b64 p, [%1], %2;\n\t"   \
        "selp.b32 %0, 1, 0, p;\n\t}" : "=r"(_done) : "r"(_m), "r"(_p) : "memory");\
    if (!_done) {                                                                 \
        asm volatile("{\n\t.reg .pred P1;\n\t"                                    \
        "WL_%=:\n\t"                                                              \
        "mbarrier.try_wait.parity.acquire.cta.shared::cta.b64 P1, [%0], %1, 0x989680;\n\t" \
        "@P1 bra.uni WD_%=;\n\tbra.uni WL_%=;\n\tWD_%=:\n\t}"                     \
        :: "r"(_m), "r"(_p) : "memory");                                          \
    } } while (0)

__device__ __forceinline__ int swz_idx(int row, int col) {
    return row * 64 + (((col >> 3) ^ (row & 7)) << 3) + (col & 7);
}
// byte address of 16B granule g in row of a 64-col fp16 tile
__device__ __forceinline__ uint32_t swz_gran(int row, int g) {
    return (uint32_t)(row * 128 + (((g ^ (row & 7))) << 4));
}

__device__ __forceinline__ void store2(float* p, float a, float b) {
    *(float2*)p = make_float2(a, b);
}
__device__ __forceinline__ void store2(__half* p, float a, float b) {
    *(__half2*)p = __floats2half2_rn(a, b);
}

// ---------------------------------------------------------------------------
// HMMA fp16 GEMM (R14 WIN config — unchanged)
// ---------------------------------------------------------------------------
namespace mg {
constexpr int KT    = 64;
constexpr int TILEB = 128 * KT * 2;
constexpr int STAGE = 2 * TILEB;
constexpr int STAGES = 3;
constexpr int MBAR_OFF = STAGES * STAGE;
constexpr int SMEM_BYTES = MBAR_OFF + 64;
}

template <typename TO>
__global__ __launch_bounds__(256, 2) void gemm_mma_kernel(
    const __half* __restrict__ At, const __half* __restrict__ Bt,
    TO* __restrict__ C, int M, int N, int K)
{
    extern __shared__ char smraw[];
    const uint32_t sb = smem_u32(smraw);
    const int tid  = threadIdx.x;
    const int bm   = blockIdx.y * 128;
    const int bn   = blockIdx.x * 128;
    const int wid  = tid >> 5, lane = tid & 31;
    const int wm   = wid & 1;
    const int wn   = wid >> 1;
    const int NK   = K >> 6;

    const __half* Abase = At + (size_t)blockIdx.y * NK * 8192;
    const __half* Bbase = Bt + (size_t)blockIdx.x * NK * 8192;
    const uint32_t mb = sb + mg::MBAR_OFF;

    if (tid == 0) {
        MBARRIER_INIT(mb,      1u);
        MBARRIER_INIT(mb + 8,  1u);
        MBARRIER_INIT(mb + 16, 1u);
        MBARRIER_INIT(mb + 24, 256u);
        MBARRIER_INIT(mb + 32, 256u);
        MBARRIER_INIT(mb + 40, 256u);
    }
    __syncthreads();

    auto issue = [&](int stage, int kblk) {
        const uint32_t m = mb + stage * 8;
        MBARRIER_EXPECT_TX(m, (uint32_t)mg::STAGE);
        const uint32_t d = sb + stage * mg::STAGE;
        bulk_cp(d,             Abase + (size_t)kblk * 8192, mg::TILEB, m);
        bulk_cp(d + mg::TILEB, Bbase + (size_t)kblk * 8192, mg::TILEB, m);
    };

    float acc[4][4][4];
#pragma unroll
    for (int i = 0; i < 4; i++)
#pragma unroll
        for (int j = 0; j < 4; j++)
#pragma unroll
            for (int q = 0; q < 4; q++) acc[i][j][q] = 0.f;

    if (tid == 0) { issue(0, 0); issue(1, 1); }

    for (int kb = 0; kb < NK; kb++) {
        const int st = kb % mg::STAGES;

        if (kb + 2 < NK && tid == 0) {
            const int kblk = kb + 2, s2 = kblk % mg::STAGES;
            if (kblk >= 3)
                MBARRIER_WAIT_PARITY(mb + 24 + s2 * 8,
                                     (uint32_t)(((kblk / 3) - 1) & 1));
            issue(s2, kblk);
        }

        MBARRIER_WAIT_PARITY(mb + st * 8, (uint32_t)((kb / 3) & 1));

        const uint32_t sA = sb + st * mg::STAGE;
        const uint32_t sB = sA + mg::TILEB;

#pragma unroll
        for (int ks = 0; ks < 4; ks++) {
            uint32_t bf[4][2];
#pragma unroll
            for (int nt = 0; nt < 4; nt++) {
                int nr = wn * 32 + nt * 8 + (lane & 7);
                int g  = 2 * ks + ((lane >> 3) & 1);
                ldsm2(bf[nt], sB + nr * 128 + ((g ^ (nr & 7)) << 4));
            }
            uint32_t a[4][4];
#pragma unroll
            for (int mt = 0; mt < 4; mt++) {
                int ar = wm * 64 + mt * 16 + (lane & 15);
                int g  = 2 * ks + (lane >> 4);
                ldsm4(a[mt], sA + ar * 128 + ((g ^ (ar & 7)) << 4));
            }
#pragma unroll
            for (int mt = 0; mt < 4; mt++)
#pragma unroll
                for (int nt = 0; nt < 4; nt++)
                    mma16816h(acc[mt][nt], a[mt], bf[nt][0], bf[nt][1]);
        }
        MBARRIER_ARRIVE(mb + 24 + st * 8);
    }

#pragma unroll
    for (int mt = 0; mt < 4; mt++) {
#pragma unroll
        for (int nt = 0; nt < 4; nt++) {
            int row = bm + wm * 64 + mt * 16 + (lane >> 2);
            int col = bn + wn * 32 + nt * 8 + (lane & 3) * 2;
            if (col < N) {
                store2(C + (size_t)row * N + col, acc[mt][nt][0], acc[mt][nt][1]);
                store2(C + (size_t)(row + 8) * N + col, acc[mt][nt][2], acc[mt][nt][3]);
            }
        }
    }
}

// ---------------------------------------------------------------------------
// fp32 row-major -> fp16 pre-swizzled 16KB tiles (unchanged)
// ---------------------------------------------------------------------------
__global__ __launch_bounds__(256) void cvt_swz_kernel(
    const float* __restrict__ src, __half* __restrict__ dst, int Mreal, int K)
{
    const int NKt = K >> 6;
    const int tile = blockIdx.x;
    const int tm = tile / NKt, tk = tile % NKt;
    __half* d = dst + (size_t)tile * 8192;
#pragma unroll
    for (int it = 0; it < 4; it++) {
        int id = it * 256 + threadIdx.x;
        int r  = id >> 3, g = id & 7;
        int grow = tm * 128 + r;
        uint32_t off = (uint32_t)(r * 64 + ((g ^ (r & 7)) << 3));
        uint4 pk;
        if (grow < Mreal) {
            const float* s = src + (size_t)grow * K + tk * 64 + g * 8;
            float4 v0 = *(const float4*)s;
            float4 v1 = *(const float4*)(s + 4);
            __half2 h0 = __floats2half2_rn(v0.x, v0.y);
            __half2 h1 = __floats2half2_rn(v0.z, v0.w);
            __half2 h2 = __floats2half2_rn(v1.x, v1.y);
            __half2 h3 = __floats2half2_rn(v1.z, v1.w);
            pk.x = *(uint32_t*)&h0; pk.y = *(uint32_t*)&h1;
            pk.z = *(uint32_t*)&h2; pk.w = *(uint32_t*)&h3;
        } else {
            pk = make_uint4(0, 0, 0, 0);
        }
        *(uint4*)(d + off) = pk;
    }
}

// ---------------------------------------------------------------------------
// Fused conv+silu (vectorized 4-wide) and dt softplus
// ---------------------------------------------------------------------------
namespace fc {
constexpr int NCONV = (cfg::BL * (cfg::D_XBC / 4) + 255) / 256;  // 4 elems/thread
constexpr int NDT   = (cfg::BL * cfg::NHEADS + 255) / 256;
}

__global__ void conv_dt_kernel(const __half* __restrict__ zx,
                               const float* __restrict__ cw,
                               const float* __restrict__ cb,
                               const float* __restrict__ dt_bias,
                               __half* __restrict__ xbc_out,
                               float* __restrict__ dt_out)
{
    int blk = blockIdx.x;
    if (blk < fc::NCONV) {
        int idx = blk * 256 + threadIdx.x;
        if (idx >= cfg::BL * (cfg::D_XBC / 4)) return;
        int j4 = (idx % (cfg::D_XBC / 4)) * 4;
        int t  = idx / (cfg::D_XBC / 4);
        int l  = t & (cfg::LSEQ - 1);
        int b  = t >> 12;

        float v[4] = { cb[j4], cb[j4 + 1], cb[j4 + 2], cb[j4 + 3] };
        const float4 w0 = *(const float4*)(cw + (j4 + 0) * 4);
        const float4 w1 = *(const float4*)(cw + (j4 + 1) * 4);
        const float4 w2 = *(const float4*)(cw + (j4 + 2) * 4);
        const float4 w3 = *(const float4*)(cw + (j4 + 3) * 4);
        const float wk[4][4] = {{w0.x, w0.y, w0.z, w0.w},
                                {w1.x, w1.y, w1.z, w1.w},
                                {w2.x, w2.y, w2.z, w2.w},
                                {w3.x, w3.y, w3.z, w3.w}};
#pragma unroll
        for (int k = 0; k < cfg::D_CONV; k++) {
            int ls = l + k - (cfg::D_CONV - 1);
            if (ls >= 0) {
                uint2 zv = *(const uint2*)(zx + (size_t)(b * cfg::LSEQ + ls) * cfg::D_IN_PROJ
                                           + cfg::D_INNER + j4);
                float2 z01 = __half22float2(*(__half2*)&zv.x);
                float2 z23 = __half22float2(*(__half2*)&zv.y);
                v[0] = fmaf(wk[0][k], z01.x, v[0]);
                v[1] = fmaf(wk[1][k], z01.y, v[1]);
                v[2] = fmaf(wk[2][k], z23.x, v[2]);
                v[3] = fmaf(wk[3][k], z23.y, v[3]);
            }
        }
        uint2 o;
        __half2 o01 = __floats2half2_rn(v[0] / (1.f + expf(-v[0])),
                                        v[1] / (1.f + expf(-v[1])));
        __half2 o23 = __floats2half2_rn(v[2] / (1.f + expf(-v[2])),
                                        v[3] / (1.f + expf(-v[3])));
        o.x = *(uint32_t*)&o01; o.y = *(uint32_t*)&o23;
        *(uint2*)(xbc_out + (size_t)t * cfg::D_XBC + j4) = o;
    } else {
        int idx = (blk - fc::NCONV) * 256 + threadIdx.x;
        if (idx >= cfg::BL * cfg::NHEADS) return;
        int h = idx & 63;
        int t = idx >> 6;
        float x = __half2float(zx[(size_t)t * cfg::D_IN_PROJ + cfg::D_INNER + cfg::D_XBC + h])
                  + dt_bias[h];
        dt_out[idx] = (x > 20.f) ? x : log1pf(expf(x));
    }
}

// ---------------------------------------------------------------------------
// SSD pass 1 (HMMA): G[n][p] = sum_l (ws[l]*B[l][n]) * (x[l][p]*dt[l]).
// Tiles stored ROW-MAJOR [l][.] with uint2 stores (conflict-free);
// transposes done by ldmatrix.trans at load time.
// ---------------------------------------------------------------------------
__global__ __launch_bounds__(256) void ssd_pass1(
    const __half* __restrict__ xbc, const float* __restrict__ dtg,
    const float* __restrict__ A_log,
    __half* __restrict__ G, float* __restrict__ acum)
{
    __shared__ __half Bw[4096];   // [l][n] * ws[l]
    __shared__ __half Xs[4096];   // [l][p] * dt[l]
    __shared__ float Acum[64], ws[64], dts[64];
    const int blk = blockIdx.x;
    const int c = blk & 63, bh = blk >> 6;
    const int h = bh & 63, b = bh >> 6;
    const int tid = threadIdx.x;
    const float Aneg = -expf(A_log[h]);
    const int l0g = c * cfg::CHUNK;

    if (tid < 64) {
        const int lane = tid & 31;
        size_t row = (size_t)(b * cfg::LSEQ + l0g + tid);
        float dtv = dtg[row * cfg::NHEADS + h];
        dts[tid] = dtv;
        float v = Aneg * dtv;
#pragma unroll
        for (int o = 1; o < 32; o <<= 1) {
            float n = __shfl_up_sync(0xffffffffu, v, o);
            if (lane >= o) v += n;
        }
        Acum[tid] = v;
    }
    __syncthreads();
    if (tid < 64) {
        float v = Acum[tid] + ((tid >= 32) ? Acum[31] : 0.f);
        Acum[tid] = v;
    }
    __syncthreads();
    if (tid < 64) {
        ws[tid] = expf(Acum[63] - Acum[tid]);
        acum[(size_t)blk * 64 + tid] = Acum[tid];
    }
    __syncthreads();

    for (int idx = tid; idx < 1024; idx += 256) {
        int l = idx >> 4, q4 = (idx & 15) * 4;
        size_t row = (size_t)(b * cfg::LSEQ + l0g + l);
        const __half* xr = xbc + row * cfg::D_XBC;
        float dtv = dts[l], wv = ws[l];
        uint2 xb = *(const uint2*)(xr + h * cfg::HEADDIM + q4);
        uint2 bb = *(const uint2*)(xr + cfg::D_INNER + q4);
        float2 x01 = __half22float2(*(__half2*)&xb.x);
        float2 x23 = __half22float2(*(__half2*)&xb.y);
        float2 b01 = __half22float2(*(__half2*)&bb.x);
        float2 b23 = __half22float2(*(__half2*)&bb.y);
        __half2 xs01 = __floats2half2_rn(x01.x * dtv, x01.y * dtv);
        __half2 xs23 = __floats2half2_rn(x23.x * dtv, x23.y * dtv);
        __half2 bw01 = __floats2half2_rn(b01.x * wv, b01.y * wv);
        __half2 bw23 = __floats2half2_rn(b23.x * wv, b23.y * wv);
        int si = swz_idx(l, q4);
        uint2 xp; xp.x = *(uint32_t*)&xs01; xp.y = *(uint32_t*)&xs23;
        uint2 bp; bp.x = *(uint32_t*)&bw01; bp.y = *(uint32_t*)&bw23;
        *(uint2*)&Xs[si] = xp;
        *(uint2*)&Bw[si] = bp;
    }
    __syncthreads();

    const int wid = tid >> 5, lane = tid & 31;
    const int wr = wid & 3, wc = wid >> 2;
    const uint32_t sBw = smem_u32(Bw), sXs = smem_u32(Xs);
    float acc[4][4];
#pragma unroll
    for (int i = 0; i < 4; i++)
#pragma unroll
        for (int j = 0; j < 4; j++) acc[i][j] = 0.f;

#pragma unroll
    for (int ks = 0; ks < 4; ks++) {
        // A = Bw^T (m = n-state, k = l): trans load from [l][n]
        uint32_t a[4];
        {
            int kr = ks * 16 + (lane & 7) + ((lane >> 4) << 3);
            int mg = wr * 2 + ((lane >> 3) & 1);
            ldsm4t(a, sBw + swz_gran(kr, mg));
        }
#pragma unroll
        for (int nt = 0; nt < 4; nt++) {
            // B = Xs (n = p, k = l): trans load from [l][p]
            uint32_t bb2[2];
            int br = ks * 16 + (lane & 15);
            int ng = wc * 4 + nt;
            ldsm2t(bb2, sXs + swz_gran(br, ng));
            mma16816h(acc[nt], a, bb2[0], bb2[1]);
        }
    }

    __half* gout = G + (size_t)blk * 4096;
    const int n0 = wr * 16 + (lane >> 2);
#pragma unroll
    for (int nt = 0; nt < 4; nt++) {
        int p = wc * 32 + nt * 8 + (lane & 3) * 2;
        __half2 v0 = __floats2half2_rn(acc[nt][0], acc[nt][1]);
        __half2 v1 = __floats2half2_rn(acc[nt][2], acc[nt][3]);
        *(__half2*)(gout + n0 * 64 + p)       = v0;
        *(__half2*)(gout + (n0 + 8) * 64 + p) = v1;
    }
}

// ---------------------------------------------------------------------------
// SSD pass 2 (unchanged)
// ---------------------------------------------------------------------------
__global__ __launch_bounds__(256) void ssd_pass2(
    const __half* __restrict__ G, const float* __restrict__ acum,
    __half* __restrict__ sprev)
{
    __shared__ float eAc[cfg::NCHUNK];
    const int bh    = blockIdx.x >> 2;
    const int slice = blockIdx.x & 3;
    const int tid   = threadIdx.x;
    if (tid < cfg::NCHUNK)
        eAc[tid] = expf(acum[((size_t)bh * cfg::NCHUNK + tid) * 64 + 63]);
    __syncthreads();

    const int f4 = slice * 256 + tid;
    float4 S = make_float4(0.f, 0.f, 0.f, 0.f);
    const size_t bhbase = (size_t)bh * cfg::NCHUNK * 4096;
    for (int c = 0; c < cfg::NCHUNK; c++) {
        const size_t base = bhbase + (size_t)c * 4096 + f4 * 4;
        uint2 sp;
        __half2 s01 = __floats2half2_rn(S.x, S.y);
        __half2 s23 = __floats2half2_rn(S.z, S.w);
        sp.x = *(uint32_t*)&s01; sp.y = *(uint32_t*)&s23;
        *(uint2*)(sprev + base) = sp;
        uint2 gp = *(const uint2*)(G + base);
        float2 g01 = __half22float2(*(__half2*)&gp.x);
        float2 g23 = __half22float2(*(__half2*)&gp.y);
        float ea = eAc[c];
        S.x = fmaf(ea, S.x, g01.x);
        S.y = fmaf(ea, S.y, g01.y);
        S.z = fmaf(ea, S.z, g23.x);
        S.w = fmaf(ea, S.w, g23.y);
    }
}

// ---------------------------------------------------------------------------
// SSD pass 3 (HMMA): row-major tiles, transposes via ldmatrix.trans.
// ---------------------------------------------------------------------------
struct P3S {
    __half Ct [4096];   // [l][n]
    __half Bt [4096];   // [s][n]
    __half Xs [4096];   // [s][p] (x*dt)
    __half Sp [4096];   // [n][p]
    __half W2 [4096];   // [l][s]
    float  Xraw[4096];  // [l][p]
    float  Acum[64], eA[64], dts[64];
};

__global__ __launch_bounds__(256) void ssd_pass3(
    const __half* __restrict__ xbc, const float* __restrict__ dtg,
    const float* __restrict__ D_param,
    const __half* __restrict__ sprev, const float* __restrict__ acum,
    __half* __restrict__ y)
{
    extern __shared__ char smraw[];
    P3S& sm = *reinterpret_cast<P3S*>(smraw);
    const int blk = blockIdx.x;
    const int c = blk & 63, bh = blk >> 6;
    const int h = bh & 63, b = bh >> 6;
    const int tid = threadIdx.x;
    const float Dh = D_param[h];
    const int l0g = c * cfg::CHUNK;

    if (tid < 64) {
        size_t row = (size_t)(b * cfg::LSEQ + l0g + tid);
        sm.dts[tid] = dtg[row * cfg::NHEADS + h];
        float a = acum[(size_t)blk * 64 + tid];
        sm.Acum[tid] = a;
        sm.eA[tid]   = expf(a);
    }
    __syncthreads();

    const __half* spin = sprev + (size_t)blk * 4096;
    for (int idx = tid; idx < 1024; idx += 256) {
        int r = idx >> 4, q4 = (idx & 15) * 4;
        size_t grow = (size_t)(b * cfg::LSEQ + l0g + r);
        const __half* xr = xbc + grow * cfg::D_XBC;
        float dtv = sm.dts[r];
        uint2 xb = *(const uint2*)(xr + h * cfg::HEADDIM + q4);
        uint2 bb = *(const uint2*)(xr + cfg::D_INNER + q4);
        uint2 cb2 = *(const uint2*)(xr + cfg::D_INNER + cfg::D_STATE + q4);
        uint2 sp = *(const uint2*)(spin + r * 64 + q4);

        int si = swz_idx(r, q4);
        *(uint2*)&sm.Ct[si] = cb2;
        *(uint2*)&sm.Bt[si] = bb;
        *(uint2*)&sm.Sp[si] = sp;         // [n][p] natural

        float2 x01 = __half22float2(*(__half2*)&xb.x);
        float2 x23 = __half22float2(*(__half2*)&xb.y);
        *(float4*)&sm.Xraw[r * 64 + q4] = make_float4(x01.x, x01.y, x23.x, x23.y);

        __half2 xs01 = __floats2half2_rn(x01.x * dtv, x01.y * dtv);
        __half2 xs23 = __floats2half2_rn(x23.x * dtv, x23.y * dtv);
        uint2 xp; xp.x = *(uint32_t*)&xs01; xp.y = *(uint32_t*)&xs23;
        *(uint2*)&sm.Xs[si] = xp;         // [s][p] natural
    }
    __syncthreads();

    const int wid = tid >> 5, lane = tid & 31;
    const int wr = wid & 3, wc = wid >> 2;
    const uint32_t sCt = smem_u32(sm.Ct), sBt = smem_u32(sm.Bt);
    const uint32_t sXs = smem_u32(sm.Xs), sSp = smem_u32(sm.Sp);
    const uint32_t sW2 = smem_u32(sm.W2);
    const int l0 = wr * 16 + (lane >> 2);

    // ---- phase A: W2 = masked-decay(C x B^T)  (A=Ct normal, B=Bt normal) ----
    {
        float accw[4][4];
#pragma unroll
        for (int i = 0; i < 4; i++)
#pragma unroll
            for (int j = 0; j < 4; j++) accw[i][j] = 0.f;
#pragma unroll
        for (int ks = 0; ks < 4; ks++) {
            uint32_t a[4];
            int ar = wr * 16 + (lane & 15);
            int ga = 2 * ks + (lane >> 4);
            ldsm4(a, sCt + swz_gran(ar, ga));
#pragma unroll
            for (int nt = 0; nt < 4; nt++) {
                uint32_t bb2[2];
                int sr = wc * 32 + nt * 8 + (lane & 7);
                int gb = 2 * ks + ((lane >> 3) & 1);
                ldsm2(bb2, sBt + swz_gran(sr, gb));
                mma16816h(accw[nt], a, bb2[0], bb2[1]);
            }
        }
        float A0 = sm.Acum[l0], A1 = sm.Acum[l0 + 8];
#pragma unroll
        for (int nt = 0; nt < 4; nt++) {
            int s0 = wc * 32 + nt * 8 + (lane & 3) * 2;
            float As0 = sm.Acum[s0], As1 = sm.Acum[s0 + 1];
            float w00 = (s0     <= l0) ? expf(A0 - As0) : 0.f;
            float w01 = (s0 + 1 <= l0) ? expf(A0 - As1) : 0.f;
            float w10 = (s0     <= l0 + 8) ? expf(A1 - As0) : 0.f;
            float w11 = (s0 + 1 <= l0 + 8) ? expf(A1 - As1) : 0.f;
            __half2 h0 = __floats2half2_rn(accw[nt][0] * w00, accw[nt][1] * w01);
            __half2 h1 = __floats2half2_rn(accw[nt][2] * w10, accw[nt][3] * w11);
            *(uint32_t*)&sm.W2[swz_idx(l0,     s0)] = *(uint32_t*)&h0;
            *(uint32_t*)&sm.W2[swz_idx(l0 + 8, s0)] = *(uint32_t*)&h1;
        }
    }
    __syncthreads();

    // ---- phase B: Y = W2 x Xs + eA*(C x Sp) + Dh*Xraw ----
    float accd[4][4], acco[4][4];
#pragma unroll
    for (int i = 0; i < 4; i++)
#pragma unroll
        for (int j = 0; j < 4; j++) { accd[i][j] = 0.f; acco[i][j] = 0.f; }

#pragma unroll
    for (int ks = 0; ks < 4; ks++) {
        uint32_t a[4];
        int ar = wr * 16 + (lane & 15);
        int ga = 2 * ks + (lane >> 4);
        ldsm4(a, sW2 + swz_gran(ar, ga));
#pragma unroll
        for (int nt = 0; nt < 4; nt++) {
            uint32_t bb2[2];
            int br = ks * 16 + (lane & 15);     // k = s rows of Xs
            int ng = wc * 4 + nt;
            ldsm2t(bb2, sXs + swz_gran(br, ng));
            mma16816h(accd[nt], a, bb2[0], bb2[1]);
        }
    }
#pragma unroll
    for (int ks = 0; ks < 4; ks++) {
        uint32_t a[4];
        int ar = wr * 16 + (lane & 15);
        int ga = 2 * ks + (lane >> 4);
        ldsm4(a, sCt + swz_gran(ar, ga));
#pragma unroll
        for (int nt = 0; nt < 4; nt++) {
            uint32_t bb2[2];
            int br = ks * 16 + (lane & 15);     // k = n rows of Sp
            int ng = wc * 4 + nt;
            ldsm2t(bb2, sSp + swz_gran(br, ng));
            mma16816h(acco[nt], a, bb2[0], bb2[1]);
        }
    }

    const float eA0 = sm.eA[l0], eA1 = sm.eA[l0 + 8];
    const size_t row0 = (size_t)(b * cfg::LSEQ + l0g + l0);
#pragma unroll
    for (int nt = 0; nt < 4; nt++) {
        int p = wc * 32 + nt * 8 + (lane & 3) * 2;
        float x00 = sm.Xraw[l0 * 64 + p],      x01 = sm.Xraw[l0 * 64 + p + 1];
        float x10 = sm.Xraw[(l0 + 8) * 64 + p], x11 = sm.Xraw[(l0 + 8) * 64 + p + 1];
        __half2 v0 = __floats2half2_rn(accd[nt][0] + eA0 * acco[nt][0] + Dh * x00,
                                       accd[nt][1] + eA0 * acco[nt][1] + Dh * x01);
        __half2 v1 = __floats2half2_rn(accd[nt][2] + eA1 * acco[nt][2] + Dh * x10,
                                       accd[nt][3] + eA1 * acco[nt][3] + Dh * x11);
        *(__half2*)(y + row0 * cfg::D_INNER + h * cfg::HEADDIM + p)       = v0;
        *(__half2*)(y + (row0 + 8) * cfg::D_INNER + h * cfg::HEADDIM + p) = v1;
    }
}

// ---------------------------------------------------------------------------
// gate + RMSNorm (fp16 y & z in) -> fp16 pre-swizzled tiles (unchanged)
// ---------------------------------------------------------------------------
__global__ __launch_bounds__(256) void gate_norm_kernel(
    const __half* __restrict__ y, const __half* __restrict__ zx,
    const float* __restrict__ nw, __half* __restrict__ nmh)
{
    __shared__ float gbuf[cfg::D_INNER];
    __shared__ float red[8];
    const int t = blockIdx.x;
    const int tid = threadIdx.x;
    const __half* yr = y + (size_t)t * cfg::D_INNER;
    const __half* zr = zx + (size_t)t * cfg::D_IN_PROJ;

    float ss = 0.f;
    for (int i = tid * 2; i < cfg::D_INNER; i += 512) {
        float2 yv = __half22float2(*(const __half2*)(yr + i));
        float2 zv = __half22float2(*(const __half2*)(zr + i));
        float g0 = yv.x * (zv.x / (1.f + expf(-zv.x)));
        float g1 = yv.y * (zv.y / (1.f + expf(-zv.y)));
        gbuf[i] = g0; gbuf[i + 1] = g1;
        ss = fmaf(g0, g0, ss);
        ss = fmaf(g1, g1, ss);
    }
#pragma unroll
    for (int o = 16; o; o >>= 1) ss += __shfl_xor_sync(0xffffffffu, ss, o);
    if ((tid & 31) == 0) red[tid >> 5] = ss;
    __syncthreads();
    if (tid < 32) {
        float v = (tid < 8) ? red[tid] : 0.f;
#pragma unroll
        for (int o = 4; o; o >>= 1) v += __shfl_xor_sync(0xffffffffu, v, o);
        if (tid == 0) red[0] = v;
    }
    __syncthreads();
    const float scale = rsqrtf(red[0] * (1.f / cfg::D_INNER) + 1e-5f);
    const int tm = t >> 7, r = t & 127;
    const size_t tmbase = (size_t)tm * (cfg::D_INNER / 64) * 8192;
    const uint32_t rx = (uint32_t)(r & 7);
    for (int i = tid; i < cfg::D_INNER; i += 256) {
        float val = gbuf[i] * scale * nw[i];
        int tk = i >> 6, g = (i >> 3) & 7, e = i & 7;
        size_t off = tmbase + (size_t)tk * 8192 + r * 64 + ((g ^ rx) << 3) + e;
        nmh[off] = __float2half_rn(val);
    }
}

// ---------------------------------------------------------------------------
// Host launch
// ---------------------------------------------------------------------------
extern "C" void kernel_launch(void* const* d_in, const int* in_sizes, int n_in,
                              void* d_out, int out_size)
{
    (void)in_sizes; (void)n_in; (void)out_size;
    const float* u       = (const float*)d_in[0];
    const float* W_in    = (const float*)d_in[1];
    const float* conv_w  = (const float*)d_in[2];
    const float* conv_b  = (const float*)d_in[3];
    const float* dt_bias = (const float*)d_in[4];
    const float* A_log   = (const float*)d_in[5];
    const float* D_param = (const float*)d_in[6];
    const float* norm_w  = (const float*)d_in[7];
    const float* W_out   = (const float*)d_in[8];
    float* out = (float*)d_out;

    void *pzx, *pxbc, *pdt, *py, *pG, *psp, *pac;
    void *puh, *pwih, *pnmh, *pwoh;
    cudaGetSymbolAddress(&pzx,  g_zx);
    cudaGetSymbolAddress(&pxbc, g_xbc);
    cudaGetSymbolAddress(&pdt,  g_dt);
    cudaGetSymbolAddress(&py,   g_y);
    cudaGetSymbolAddress(&pG,   g_G);
    cudaGetSymbolAddress(&psp,  g_sprev);
    cudaGetSymbolAddress(&pac,  g_acum);
    cudaGetSymbolAddress(&puh,  g_uh);
    cudaGetSymbolAddress(&pwih, g_wih);
    cudaGetSymbolAddress(&pnmh, g_nmh);
    cudaGetSymbolAddress(&pwoh, g_woh);
    __half* zx  = (__half*)pzx;
    __half* xbc = (__half*)pxbc;
    float*  dtb = (float*)pdt;
    __half* yb  = (__half*)py;
    __half* Gb  = (__half*)pG;
    __half* spb = (__half*)psp;
    float*  acb = (float*)pac;
    __half* uh  = (__half*)puh;
    __half* wih = (__half*)pwih;
    __half* nmh = (__half*)pnmh;
    __half* woh = (__half*)pwoh;

    cudaFuncSetAttribute(gemm_mma_kernel<__half>,
                         cudaFuncAttributeMaxDynamicSharedMemorySize, mg::SMEM_BYTES);
    cudaFuncSetAttribute(gemm_mma_kernel<float>,
                         cudaFuncAttributeMaxDynamicSharedMemorySize, mg::SMEM_BYTES);
    cudaFuncSetAttribute(ssd_pass3, cudaFuncAttributeMaxDynamicSharedMemorySize,
                         (int)sizeof(P3S));

    cvt_swz_kernel<<<(cfg::BL / 128) * (cfg::D_MODEL / 64), 256>>>(
        u, uh, cfg::BL, cfg::D_MODEL);
    cvt_swz_kernel<<<(cfg::N1_PAD / 128) * (cfg::D_MODEL / 64), 256>>>(
        W_in, wih, cfg::D_IN_PROJ, cfg::D_MODEL);
    cvt_swz_kernel<<<(cfg::D_MODEL / 128) * (cfg::D_INNER / 64), 256>>>(
        W_out, woh, cfg::D_MODEL, cfg::D_INNER);

    // GEMM1: zx(fp16) = u @ W_in^T
    {
        dim3 grid(cfg::N1_PAD / 128, cfg::BL / 128);
        gemm_mma_kernel<__half><<<grid, 256, mg::SMEM_BYTES>>>(
            uh, wih, zx, cfg::BL, cfg::D_IN_PROJ, cfg::D_MODEL);
    }
    conv_dt_kernel<<<fc::NCONV + fc::NDT, 256>>>(zx, conv_w, conv_b, dt_bias, xbc, dtb);
    ssd_pass1<<<cfg::NBH * cfg::NCHUNK, 256>>>(xbc, dtb, A_log, Gb, acb);
    ssd_pass2<<<cfg::NBH * 4, 256>>>(Gb, acb, spb);
    ssd_pass3<<<cfg::NBH * cfg::NCHUNK, 256, sizeof(P3S)>>>(
        xbc, dtb, D_param, spb, acb, yb);
    gate_norm_kernel<<<cfg::BL, 256>>>(yb, zx, norm_w, nmh);
    // GEMM2: out(fp32) = nm @ W_out^T
    {
        dim3 grid(cfg::D_MODEL / 128, cfg::BL / 128);
        gemm_mma_kernel<float><<<grid, 256, mg::SMEM_BYTES>>>(
            nmh, woh, out, cfg::BL, cfg::D_MODEL, cfg::D_INNER);
    }
}